// round 1
// baseline (speedup 1.0000x reference)
#include <cuda_runtime.h>
#include <cmath>

#define B_    2
#define L_    2048
#define DM_   2048
#define DIP_  8512
#define DI_   4096
#define CDIM_ 4352
#define NH_   64
#define HD_   64
#define DS_   128
#define CH_   256
#define NC_   8
#define DCV   4

// ---------------- scratch (device globals; no allocation) ----------------
__device__ float g_zx  [(size_t)B_*L_*DIP_];        // zxbcdt = u @ w_in
__device__ float g_xBC [(size_t)B_*L_*CDIM_];       // conv+silu output
__device__ float g_dtv [(size_t)B_*L_*NH_];         // softplus(dt + bias)
__device__ float g_Acs [(size_t)B_*NC_*NH_*CH_];    // per-chunk inclusive cumsum of dA
__device__ float g_CB  [(size_t)B_*NC_*CH_*CH_];    // C @ B^T per (b,chunk)
__device__ float g_st  [(size_t)B_*NC_*NH_*HD_*DS_];// per-chunk end states
__device__ float g_is  [(size_t)B_*NC_*NH_*HD_*DS_];// init states (pre-chunk)
__device__ float g_y   [(size_t)B_*L_*DI_];         // SSD output + D skip

// ---------------- K1: zxbcdt = u @ w_in  (fp32, 128x64 tile) ----------------
__global__ __launch_bounds__(256) void gemm_in_kernel(const float* __restrict__ u,
                                                      const float* __restrict__ w) {
    __shared__ float As[16][136];   // [k][m], padded
    __shared__ float Bs[16][64];    // [k][n]
    const int m0 = blockIdx.y * 128;
    const int n0 = blockIdx.x * 64;
    const int tid = threadIdx.x;
    const int ni = tid & 15, mi = tid >> 4;   // micro: 8(m) x 4(n)

    float acc[8][4];
#pragma unroll
    for (int i = 0; i < 8; i++)
#pragma unroll
        for (int j = 0; j < 4; j++) acc[i][j] = 0.f;

    for (int kt = 0; kt < DM_; kt += 16) {
        // load A tile (128 x 16) transposed into As[k][m]
#pragma unroll
        for (int i = 0; i < 2; i++) {
            int slot = tid + i * 256;          // 0..511
            int m = slot >> 2, kg = (slot & 3) << 2;
            float4 v = *(const float4*)(u + (size_t)(m0 + m) * DM_ + kt + kg);
            As[kg + 0][m] = v.x; As[kg + 1][m] = v.y;
            As[kg + 2][m] = v.z; As[kg + 3][m] = v.w;
        }
        // load B tile (16 x 64)
        {
            int kk = tid >> 4, nn = (tid & 15) << 2;
            *(float4*)&Bs[kk][nn] = *(const float4*)(w + (size_t)(kt + kk) * DIP_ + n0 + nn);
        }
        __syncthreads();
#pragma unroll
        for (int k = 0; k < 16; k++) {
            float a[8], b[4];
            *(float4*)&a[0] = *(float4*)&As[k][mi * 8];
            *(float4*)&a[4] = *(float4*)&As[k][mi * 8 + 4];
            *(float4*)&b[0] = *(float4*)&Bs[k][ni * 4];
#pragma unroll
            for (int mm = 0; mm < 8; mm++)
#pragma unroll
                for (int nn = 0; nn < 4; nn++) acc[mm][nn] += a[mm] * b[nn];
        }
        __syncthreads();
    }
#pragma unroll
    for (int mm = 0; mm < 8; mm++) {
        float4 o; o.x = acc[mm][0]; o.y = acc[mm][1]; o.z = acc[mm][2]; o.w = acc[mm][3];
        *(float4*)&g_zx[(size_t)(m0 + mi * 8 + mm) * DIP_ + n0 + ni * 4] = o;
    }
}

// ---------------- K2: causal conv(4) + bias + silu ----------------
__global__ void conv_kernel(const float* __restrict__ conv_w, const float* __restrict__ conv_b) {
    int idx = blockIdx.x * 256 + threadIdx.x;      // B*L*CDIM exactly
    int ch = idx % CDIM_;
    int bl = idx / CDIM_;
    int l = bl % L_;
    float acc = conv_b[ch];
#pragma unroll
    for (int k = 0; k < DCV; k++) {
        int ls = l + k - (DCV - 1);
        if (ls >= 0)
            acc += g_zx[(size_t)(bl - l + ls) * DIP_ + DI_ + ch] * conv_w[ch * DCV + k];
    }
    g_xBC[(size_t)idx] = acc / (1.f + __expf(-acc));
}

// ---------------- K3: dt = softplus(raw + bias) ----------------
__global__ void dt_kernel(const float* __restrict__ dt_bias) {
    int idx = blockIdx.x * 256 + threadIdx.x;      // B*L*NH
    int h = idx % NH_;
    float x = g_zx[(size_t)(idx / NH_) * DIP_ + DI_ + CDIM_ + h] + dt_bias[h];
    g_dtv[idx] = (x > 20.f) ? x : log1pf(expf(x));
}

// ---------------- K4: per-chunk inclusive cumsum of dA = dt*A ----------------
__global__ void acs_kernel(const float* __restrict__ A_log) {
    int blk = blockIdx.x;                 // (b*NC + c)*NH + h
    int h = blk % NH_;
    int bc = blk / NH_;
    int c = bc % NC_;
    int b = bc / NC_;
    int t = threadIdx.x;
    __shared__ float s[CH_];
    float A = -__expf(A_log[h]);
    s[t] = g_dtv[(size_t)(b * L_ + c * CH_ + t) * NH_ + h] * A;
    __syncthreads();
    for (int off = 1; off < CH_; off <<= 1) {
        float v = (t >= off) ? s[t - off] : 0.f;
        __syncthreads();
        s[t] += v;
        __syncthreads();
    }
    g_Acs[(size_t)blk * CH_ + t] = s[t];
}

// ---------------- K5: CB[t][s] = sum_n C[t,n]*B[s,n] per (b,chunk) ----------------
__global__ __launch_bounds__(256) void cb_kernel() {
    int z = blockIdx.z;                  // b*NC + c
    int b = z / NC_, c = z % NC_;
    int t0 = blockIdx.y * 64, s0 = blockIdx.x * 64;
    __shared__ float Ct[64][68];         // [n][t]
    __shared__ float Bt[64][68];         // [n][s]
    int tid = threadIdx.x;
    int ti = tid >> 4, si = tid & 15;
    float acc[4][4];
#pragma unroll
    for (int i = 0; i < 4; i++)
#pragma unroll
        for (int j = 0; j < 4; j++) acc[i][j] = 0.f;
    const float* xbase = g_xBC + (size_t)(b * L_ + c * CH_) * CDIM_;
    for (int nh = 0; nh < DS_; nh += 64) {
        __syncthreads();
#pragma unroll
        for (int i = 0; i < 4; i++) {
            int slot = tid + i * 256;              // 0..1023
            int row = slot & 63, ng = (slot >> 6) << 2;
            float4 cv = *(const float4*)(xbase + (size_t)(t0 + row) * CDIM_ + DI_ + DS_ + nh + ng);
            Ct[ng + 0][row] = cv.x; Ct[ng + 1][row] = cv.y;
            Ct[ng + 2][row] = cv.z; Ct[ng + 3][row] = cv.w;
            float4 bv = *(const float4*)(xbase + (size_t)(s0 + row) * CDIM_ + DI_ + nh + ng);
            Bt[ng + 0][row] = bv.x; Bt[ng + 1][row] = bv.y;
            Bt[ng + 2][row] = bv.z; Bt[ng + 3][row] = bv.w;
        }
        __syncthreads();
#pragma unroll 8
        for (int n = 0; n < 64; n++) {
            float a[4], bb[4];
            *(float4*)&a[0]  = *(float4*)&Ct[n][ti * 4];
            *(float4*)&bb[0] = *(float4*)&Bt[n][si * 4];
#pragma unroll
            for (int q = 0; q < 4; q++)
#pragma unroll
                for (int r = 0; r < 4; r++) acc[q][r] += a[q] * bb[r];
        }
    }
#pragma unroll
    for (int q = 0; q < 4; q++) {
        float4 o; o.x = acc[q][0]; o.y = acc[q][1]; o.z = acc[q][2]; o.w = acc[q][3];
        *(float4*)&g_CB[((size_t)z * CH_ + t0 + ti * 4 + q) * CH_ + s0 + si * 4] = o;
    }
}

// ---------------- K6: chunk states S[p,n] = sum_t exp(AcsL-Acs[t])*dt[t]*x[t,p]*B[t,n] ----------------
__global__ __launch_bounds__(256) void state_kernel() {
    int bid = blockIdx.x;                 // (b*NC + c)*NH + h
    int h = bid % NH_;
    int bc = bid / NH_;
    int c = bc % NC_;
    int b = bc / NC_;
    __shared__ float wx[32][64];          // (w*dt*x)[t][p]
    __shared__ float Bt[32][128];         // B[t][n]
    __shared__ float wv[32];
    int tid = threadIdx.x;
    int pi = tid >> 4, ni = tid & 15;
    int p0 = pi * 4, n0 = ni * 8;
    float acc[4][8];
#pragma unroll
    for (int i = 0; i < 4; i++)
#pragma unroll
        for (int j = 0; j < 8; j++) acc[i][j] = 0.f;
    const float* xbc = g_xBC + (size_t)(b * L_ + c * CH_) * CDIM_;
    int ab = ((b * NC_ + c) * NH_ + h) * CH_;
    float acsLast = g_Acs[(size_t)ab + CH_ - 1];

    for (int kt = 0; kt < CH_; kt += 32) {
        __syncthreads();
        if (tid < 32) {
            int r = kt + tid;
            wv[tid] = __expf(acsLast - g_Acs[(size_t)ab + r]) *
                      g_dtv[(size_t)(b * L_ + c * CH_ + r) * NH_ + h];
        }
        __syncthreads();
#pragma unroll
        for (int i = 0; i < 2; i++) {
            int slot = tid + i * 256;             // 0..511
            int row = slot >> 4, p4 = (slot & 15) << 2;
            float4 v = *(const float4*)(xbc + (size_t)(kt + row) * CDIM_ + h * HD_ + p4);
            float wgt = wv[row];
            v.x *= wgt; v.y *= wgt; v.z *= wgt; v.w *= wgt;
            *(float4*)&wx[row][p4] = v;
        }
#pragma unroll
        for (int i = 0; i < 4; i++) {
            int slot = tid + i * 256;             // 0..1023
            int row = slot >> 5, n4 = (slot & 31) << 2;
            *(float4*)&Bt[row][n4] = *(const float4*)(xbc + (size_t)(kt + row) * CDIM_ + DI_ + n4);
        }
        __syncthreads();
#pragma unroll 8
        for (int k = 0; k < 32; k++) {
            float a[4], bb[8];
            *(float4*)&a[0]  = *(float4*)&wx[k][p0];
            *(float4*)&bb[0] = *(float4*)&Bt[k][n0];
            *(float4*)&bb[4] = *(float4*)&Bt[k][n0 + 4];
#pragma unroll
            for (int q = 0; q < 4; q++)
#pragma unroll
                for (int r = 0; r < 8; r++) acc[q][r] += a[q] * bb[r];
        }
    }
    size_t base = (size_t)bid * HD_ * DS_;
#pragma unroll
    for (int q = 0; q < 4; q++) {
        float4 o1, o2;
        o1.x = acc[q][0]; o1.y = acc[q][1]; o1.z = acc[q][2]; o1.w = acc[q][3];
        o2.x = acc[q][4]; o2.y = acc[q][5]; o2.z = acc[q][6]; o2.w = acc[q][7];
        *(float4*)&g_st[base + (size_t)(p0 + q) * DS_ + n0]     = o1;
        *(float4*)&g_st[base + (size_t)(p0 + q) * DS_ + n0 + 4] = o2;
    }
}

// ---------------- K7: inter-chunk state recurrence ----------------
__global__ void rec_kernel() {
    int bid = blockIdx.x;      // b*NH + h
    int h = bid % NH_;
    int b = bid / NH_;
    int tid = threadIdx.x;
    float S[32];
#pragma unroll
    for (int k = 0; k < 32; k++) S[k] = 0.f;
    for (int c = 0; c < NC_; c++) {
        int blk = (b * NC_ + c) * NH_ + h;
        size_t base = (size_t)blk * HD_ * DS_;
        float ef = __expf(g_Acs[(size_t)blk * CH_ + CH_ - 1]);
#pragma unroll
        for (int k = 0; k < 32; k++) {
            size_t e = base + (size_t)k * 256 + tid;
            g_is[e] = S[k];
            S[k] = S[k] * ef + g_st[e];
        }
    }
}

// ---------------- K8: fused Y = Yd + Yo + D*x per (b,chunk,head) ----------------
__global__ __launch_bounds__(256, 1) void y_kernel(const float* __restrict__ D_skip) {
    extern __shared__ float sm[];
    float* x_s   = sm;                   // 256*64 : x[s][p]
    float* w_s   = x_s + 256 * 64;       // 64*256 : weight tile [k][t]
    float* st_s  = w_s + 64 * 256;       // 128*64 : S^T [n][p]
    float* acs_s = st_s + 128 * 64;      // 256
    float* dtv_s = acs_s + 256;          // 256
    float* einv_s = dtv_s + 256;         // 64

    int bid = blockIdx.x;                // (b*NC + c)*NH + h
    int h = bid % NH_;
    int bc = bid / NH_;
    int c = bc % NC_;
    int b = bc / NC_;
    int tid = threadIdx.x;
    int tg = tid >> 3, pg = tid & 7;     // micro 8(t) x 8(p)
    int t = tid;

    const float* xbc = g_xBC + (size_t)(b * L_ + c * CH_) * CDIM_;
    const float* cbrow = g_CB + ((size_t)(b * NC_ + c) * CH_ + t) * CH_;
    const float* isb = g_is + (size_t)bid * HD_ * DS_;
    int ab = bid * CH_;

    for (int slot = tid; slot < 4096; slot += 256) {
        int row = slot >> 4, p4 = (slot & 15) << 2;
        *(float4*)&x_s[row * 64 + p4] = *(const float4*)(xbc + (size_t)row * CDIM_ + h * HD_ + p4);
    }
    for (int slot = tid; slot < 2048; slot += 256) {
        int p = slot & 63, ng = (slot >> 6) << 2;
        float4 v = *(const float4*)(isb + (size_t)p * DS_ + ng);
        st_s[(ng + 0) * 64 + p] = v.x;
        st_s[(ng + 1) * 64 + p] = v.y;
        st_s[(ng + 2) * 64 + p] = v.z;
        st_s[(ng + 3) * 64 + p] = v.w;
    }
    acs_s[tid] = g_Acs[(size_t)ab + tid];
    dtv_s[tid] = g_dtv[(size_t)(b * L_ + c * CH_ + tid) * NH_ + h];

    float acc[8][8];
#pragma unroll
    for (int i = 0; i < 8; i++)
#pragma unroll
        for (int j = 0; j < 8; j++) acc[i][j] = 0.f;

    // Phase A: intra-chunk Yd  (K-tiles of 64 over s)
    for (int k0 = 0; k0 < CH_; k0 += 64) {
        __syncthreads();
        if (tid < 64) {
            int sb = k0 + (tid & 0x30);
            einv_s[tid] = __expf(fminf(acs_s[sb] - acs_s[k0 + tid], 80.f));
        }
        __syncthreads();
#pragma unroll
        for (int sub = 0; sub < 4; sub++) {
            int sbase = k0 + sub * 16;
            if (t >= sbase) {
                float et = __expf(acs_s[t] - acs_s[sbase]);
#pragma unroll
                for (int jj = 0; jj < 16; jj += 4) {
                    float4 cb4 = *(const float4*)(cbrow + sbase + jj);
                    int s0q = sbase + jj;
                    float v0 = et * einv_s[sub * 16 + jj + 0] * cb4.x * dtv_s[s0q + 0];
                    float v1 = et * einv_s[sub * 16 + jj + 1] * cb4.y * dtv_s[s0q + 1];
                    float v2 = et * einv_s[sub * 16 + jj + 2] * cb4.z * dtv_s[s0q + 2];
                    float v3 = et * einv_s[sub * 16 + jj + 3] * cb4.w * dtv_s[s0q + 3];
                    w_s[(sub * 16 + jj + 0) * 256 + t] = (s0q + 0 <= t) ? v0 : 0.f;
                    w_s[(sub * 16 + jj + 1) * 256 + t] = (s0q + 1 <= t) ? v1 : 0.f;
                    w_s[(sub * 16 + jj + 2) * 256 + t] = (s0q + 2 <= t) ? v2 : 0.f;
                    w_s[(sub * 16 + jj + 3) * 256 + t] = (s0q + 3 <= t) ? v3 : 0.f;
                }
            } else {
#pragma unroll
                for (int j = 0; j < 16; j++) w_s[(sub * 16 + j) * 256 + t] = 0.f;
            }
        }
        __syncthreads();
        if (tg * 8 + 7 >= k0) {
#pragma unroll 4
            for (int k = 0; k < 64; k++) {
                float a[8], bb[8];
                *(float4*)&a[0]  = *(float4*)&w_s[k * 256 + tg * 8];
                *(float4*)&a[4]  = *(float4*)&w_s[k * 256 + tg * 8 + 4];
                *(float4*)&bb[0] = *(float4*)&x_s[(k0 + k) * 64 + pg * 8];
                *(float4*)&bb[4] = *(float4*)&x_s[(k0 + k) * 64 + pg * 8 + 4];
#pragma unroll
                for (int mm = 0; mm < 8; mm++)
#pragma unroll
                    for (int nn = 0; nn < 8; nn++) acc[mm][nn] += a[mm] * bb[nn];
            }
        }
    }

    // Phase B: inter-chunk Yo = exp(Acs[t]) * C[t] @ S^T
    float et0 = __expf(acs_s[t]);
    for (int n0 = 0; n0 < DS_; n0 += 64) {
        __syncthreads();
#pragma unroll
        for (int j = 0; j < 64; j += 4) {
            float4 c4 = *(const float4*)(xbc + (size_t)t * CDIM_ + DI_ + DS_ + n0 + j);
            w_s[(j + 0) * 256 + t] = c4.x * et0;
            w_s[(j + 1) * 256 + t] = c4.y * et0;
            w_s[(j + 2) * 256 + t] = c4.z * et0;
            w_s[(j + 3) * 256 + t] = c4.w * et0;
        }
        __syncthreads();
#pragma unroll 4
        for (int k = 0; k < 64; k++) {
            float a[8], bb[8];
            *(float4*)&a[0]  = *(float4*)&w_s[k * 256 + tg * 8];
            *(float4*)&a[4]  = *(float4*)&w_s[k * 256 + tg * 8 + 4];
            *(float4*)&bb[0] = *(float4*)&st_s[(n0 + k) * 64 + pg * 8];
            *(float4*)&bb[4] = *(float4*)&st_s[(n0 + k) * 64 + pg * 8 + 4];
#pragma unroll
            for (int mm = 0; mm < 8; mm++)
#pragma unroll
                for (int nn = 0; nn < 8; nn++) acc[mm][nn] += a[mm] * bb[nn];
        }
    }

    // Epilogue: + D * x, write y
    float dsk = D_skip[h];
#pragma unroll
    for (int mm = 0; mm < 8; mm++) {
        int tt = tg * 8 + mm;
        size_t orow = (size_t)(b * L_ + c * CH_ + tt) * DI_ + h * HD_ + pg * 8;
        float4 o1, o2;
        o1.x = acc[mm][0] + dsk * x_s[tt * 64 + pg * 8 + 0];
        o1.y = acc[mm][1] + dsk * x_s[tt * 64 + pg * 8 + 1];
        o1.z = acc[mm][2] + dsk * x_s[tt * 64 + pg * 8 + 2];
        o1.w = acc[mm][3] + dsk * x_s[tt * 64 + pg * 8 + 3];
        o2.x = acc[mm][4] + dsk * x_s[tt * 64 + pg * 8 + 4];
        o2.y = acc[mm][5] + dsk * x_s[tt * 64 + pg * 8 + 5];
        o2.z = acc[mm][6] + dsk * x_s[tt * 64 + pg * 8 + 6];
        o2.w = acc[mm][7] + dsk * x_s[tt * 64 + pg * 8 + 7];
        *(float4*)&g_y[orow]     = o1;
        *(float4*)&g_y[orow + 4] = o2;
    }
}

// ---------------- K9: gate (silu(z)) + RMSNorm ----------------
__global__ void gate_kernel(const float* __restrict__ norm_w, float* __restrict__ out) {
    int row = blockIdx.x;           // b*L + l
    int tid = threadIdx.x;
    __shared__ float yg_s[DI_];
    __shared__ float red[256];
    float ss = 0.f;
    for (int i = tid; i < DI_; i += 256) {
        float yv = g_y[(size_t)row * DI_ + i];
        float z = g_zx[(size_t)row * DIP_ + i];
        float yg = yv * (z / (1.f + __expf(-z)));
        yg_s[i] = yg;
        ss += yg * yg;
    }
    red[tid] = ss;
    __syncthreads();
    for (int off = 128; off > 0; off >>= 1) {
        if (tid < off) red[tid] += red[tid + off];
        __syncthreads();
    }
    float r = rsqrtf(red[0] / (float)DI_ + 1e-5f);
    for (int i = tid; i < DI_; i += 256)
        out[(size_t)row * DI_ + i] = yg_s[i] * r * norm_w[i];
}

// ---------------- launch ----------------
extern "C" void kernel_launch(void* const* d_in, const int* in_sizes, int n_in,
                              void* d_out, int out_size) {
    const float* u       = (const float*)d_in[0];
    const float* w_in    = (const float*)d_in[1];
    const float* conv_w  = (const float*)d_in[2];
    const float* conv_b  = (const float*)d_in[3];
    const float* dt_bias = (const float*)d_in[4];
    const float* A_log   = (const float*)d_in[5];
    const float* D_skip  = (const float*)d_in[6];
    const float* norm_w  = (const float*)d_in[7];
    float* out = (float*)d_out;

    cudaFuncSetAttribute(y_kernel, cudaFuncAttributeMaxDynamicSharedMemorySize, 166144);

    gemm_in_kernel<<<dim3(DIP_ / 64, (B_ * L_) / 128), 256>>>(u, w_in);
    conv_kernel<<<(B_ * L_ * CDIM_) / 256, 256>>>(conv_w, conv_b);
    dt_kernel<<<(B_ * L_ * NH_) / 256, 256>>>(dt_bias);
    acs_kernel<<<B_ * NC_ * NH_, CH_>>>(A_log);
    cb_kernel<<<dim3(4, 4, B_ * NC_), 256>>>();
    state_kernel<<<B_ * NC_ * NH_, 256>>>();
    rec_kernel<<<B_ * NH_, 256>>>();
    y_kernel<<<B_ * NC_ * NH_, 256, 166144>>>(D_skip);
    gate_kernel<<<B_ * L_, 256>>>(norm_w, out);
}

// round 2
// speedup vs baseline: 1.8556x; 1.8556x over previous
#include <cuda_runtime.h>
#include <cstdint>
#include <cmath>

#define B_    2
#define L_    2048
#define DM_   2048
#define DIP_  8512
#define DI_   4096
#define CDIM_ 4352
#define NH_   64
#define HD_   64
#define DS_   128
#define CH_   256
#define NC_   8
#define DCV   4

// ---------------- scratch (device globals; no allocation) ----------------
__device__ float g_zx  [(size_t)B_*L_*DIP_];        // zxbcdt = u @ w_in (tf32 path)
__device__ float g_xBC [(size_t)B_*L_*CDIM_];       // conv+silu output
__device__ float g_dtv [(size_t)B_*L_*NH_];         // softplus(dt + bias)  (exact fp32)
__device__ float g_Acs [(size_t)B_*NC_*NH_*CH_];    // per-chunk inclusive cumsum of dA
__device__ float g_CB  [(size_t)B_*NC_*CH_*CH_];    // C @ B^T per (b,chunk)
__device__ float g_st  [(size_t)B_*NC_*NH_*HD_*DS_];// per-chunk end states
__device__ float g_is  [(size_t)B_*NC_*NH_*HD_*DS_];// init states (pre-chunk)
__device__ float g_y   [(size_t)B_*L_*DI_];         // SSD output + D skip

__device__ __forceinline__ uint32_t f2tf32(float x) {
    uint32_t r;
    asm("cvt.rna.tf32.f32 %0, %1;" : "=r"(r) : "f"(x));
    return r;
}

// ---------------- K1: zxbcdt = u @ w_in  (tf32 tensor cores) ----------------
// block tile 128(M) x 64(N), K-tile 32, 8 warps (4m x 2n), warp tile 32x32
__global__ __launch_bounds__(256, 2) void gemm_tf32_kernel(const float* __restrict__ u,
                                                           const float* __restrict__ w) {
    __shared__ uint32_t As[128][36];   // [m][k], pad 36 -> conflict-free frag reads
    __shared__ uint32_t Bs[32][72];    // [k][n], pad 72 -> conflict-free frag reads

    const int tid = threadIdx.x;
    const int m0 = blockIdx.y * 128;
    const int n0 = blockIdx.x * 64;
    const int lane = tid & 31, wid = tid >> 5;
    const int wm = wid >> 1, wn = wid & 1;
    const int grp = lane >> 2, tig = lane & 3;

    float acc[2][4][4];
#pragma unroll
    for (int mt = 0; mt < 2; mt++)
#pragma unroll
        for (int nt = 0; nt < 4; nt++)
#pragma unroll
            for (int i = 0; i < 4; i++) acc[mt][nt][i] = 0.f;

    float4 aR[4], bR[2];

    // prefetch k-tile 0
#pragma unroll
    for (int i = 0; i < 4; i++) {
        int slot = tid + i * 256;
        int row = slot >> 3, c4 = (slot & 7) << 2;
        aR[i] = *(const float4*)(u + (size_t)(m0 + row) * DM_ + c4);
    }
#pragma unroll
    for (int i = 0; i < 2; i++) {
        int slot = tid + i * 256;
        int row = slot >> 4, c4 = (slot & 15) << 2;
        bR[i] = *(const float4*)(w + (size_t)row * DIP_ + n0 + c4);
    }

    for (int kt = 0; kt < DM_; kt += 32) {
        // regs -> smem (with rna tf32 rounding)
#pragma unroll
        for (int i = 0; i < 4; i++) {
            int slot = tid + i * 256;
            int row = slot >> 3, c4 = (slot & 7) << 2;
            uint4 p;
            p.x = f2tf32(aR[i].x); p.y = f2tf32(aR[i].y);
            p.z = f2tf32(aR[i].z); p.w = f2tf32(aR[i].w);
            *(uint4*)&As[row][c4] = p;
        }
#pragma unroll
        for (int i = 0; i < 2; i++) {
            int slot = tid + i * 256;
            int row = slot >> 4, c4 = (slot & 15) << 2;
            uint4 p;
            p.x = f2tf32(bR[i].x); p.y = f2tf32(bR[i].y);
            p.z = f2tf32(bR[i].z); p.w = f2tf32(bR[i].w);
            *(uint4*)&Bs[row][c4] = p;
        }
        __syncthreads();

        // prefetch next k-tile
        if (kt + 32 < DM_) {
#pragma unroll
            for (int i = 0; i < 4; i++) {
                int slot = tid + i * 256;
                int row = slot >> 3, c4 = (slot & 7) << 2;
                aR[i] = *(const float4*)(u + (size_t)(m0 + row) * DM_ + kt + 32 + c4);
            }
#pragma unroll
            for (int i = 0; i < 2; i++) {
                int slot = tid + i * 256;
                int row = slot >> 4, c4 = (slot & 15) << 2;
                bR[i] = *(const float4*)(w + (size_t)(kt + 32 + row) * DIP_ + n0 + c4);
            }
        }

#pragma unroll
        for (int ks = 0; ks < 4; ks++) {
            uint32_t a[2][4], b[4][2];
#pragma unroll
            for (int mt = 0; mt < 2; mt++) {
                int r0 = wm * 32 + mt * 16 + grp;
                a[mt][0] = As[r0][ks * 8 + tig];
                a[mt][1] = As[r0 + 8][ks * 8 + tig];
                a[mt][2] = As[r0][ks * 8 + tig + 4];
                a[mt][3] = As[r0 + 8][ks * 8 + tig + 4];
            }
#pragma unroll
            for (int nt = 0; nt < 4; nt++) {
                int cc = wn * 32 + nt * 8 + grp;
                b[nt][0] = Bs[ks * 8 + tig][cc];
                b[nt][1] = Bs[ks * 8 + tig + 4][cc];
            }
#pragma unroll
            for (int mt = 0; mt < 2; mt++)
#pragma unroll
                for (int nt = 0; nt < 4; nt++) {
                    asm volatile(
                        "mma.sync.aligned.m16n8k8.row.col.f32.tf32.tf32.f32 "
                        "{%0,%1,%2,%3}, {%4,%5,%6,%7}, {%8,%9}, {%0,%1,%2,%3};"
                        : "+f"(acc[mt][nt][0]), "+f"(acc[mt][nt][1]),
                          "+f"(acc[mt][nt][2]), "+f"(acc[mt][nt][3])
                        : "r"(a[mt][0]), "r"(a[mt][1]), "r"(a[mt][2]), "r"(a[mt][3]),
                          "r"(b[nt][0]), "r"(b[nt][1]));
                }
        }
        __syncthreads();
    }

#pragma unroll
    for (int mt = 0; mt < 2; mt++)
#pragma unroll
        for (int nt = 0; nt < 4; nt++) {
            int row = m0 + wm * 32 + mt * 16 + grp;
            int col = n0 + wn * 32 + nt * 8 + tig * 2;
            float2 v0, v1;
            v0.x = acc[mt][nt][0]; v0.y = acc[mt][nt][1];
            v1.x = acc[mt][nt][2]; v1.y = acc[mt][nt][3];
            *(float2*)&g_zx[(size_t)row * DIP_ + col]       = v0;
            *(float2*)&g_zx[(size_t)(row + 8) * DIP_ + col] = v1;
        }
}

// ---------------- K1b: exact fp32 dt = softplus(u @ w_in[:, dt cols] + bias) ----------------
__global__ __launch_bounds__(256) void dtg_kernel(const float* __restrict__ u,
                                                  const float* __restrict__ w,
                                                  const float* __restrict__ dt_bias) {
    __shared__ float Ast[16][68];   // [k][m]
    __shared__ float Bst[16][68];   // [k][h]
    const int m0 = blockIdx.x * 64;
    const int NOFF = DI_ + CDIM_;   // 8448
    const int tid = threadIdx.x;
    const int mi = tid >> 4, ni = tid & 15;

    float acc[4][4];
#pragma unroll
    for (int i = 0; i < 4; i++)
#pragma unroll
        for (int j = 0; j < 4; j++) acc[i][j] = 0.f;

    for (int kt = 0; kt < DM_; kt += 16) {
        {
            int m = tid >> 2, kg = (tid & 3) << 2;
            float4 v = *(const float4*)(u + (size_t)(m0 + m) * DM_ + kt + kg);
            Ast[kg + 0][m] = v.x; Ast[kg + 1][m] = v.y;
            Ast[kg + 2][m] = v.z; Ast[kg + 3][m] = v.w;
        }
        {
            int k = tid >> 4, n4 = (tid & 15) << 2;
            *(float4*)&Bst[k][n4] = *(const float4*)(w + (size_t)(kt + k) * DIP_ + NOFF + n4);
        }
        __syncthreads();
#pragma unroll
        for (int k = 0; k < 16; k++) {
            float a[4], b[4];
            *(float4*)&a[0] = *(float4*)&Ast[k][mi * 4];
            *(float4*)&b[0] = *(float4*)&Bst[k][ni * 4];
#pragma unroll
            for (int i = 0; i < 4; i++)
#pragma unroll
                for (int j = 0; j < 4; j++) acc[i][j] += a[i] * b[j];
        }
        __syncthreads();
    }
#pragma unroll
    for (int i = 0; i < 4; i++)
#pragma unroll
        for (int j = 0; j < 4; j++) {
            int h = ni * 4 + j;
            float x = acc[i][j] + dt_bias[h];
            float sp = (x > 20.f) ? x : log1pf(expf(x));
            g_dtv[(size_t)(m0 + mi * 4 + i) * NH_ + h] = sp;
        }
}

// ---------------- K2: causal conv(4) + bias + silu ----------------
__global__ void conv_kernel(const float* __restrict__ conv_w, const float* __restrict__ conv_b) {
    int idx = blockIdx.x * 256 + threadIdx.x;      // B*L*CDIM exactly
    int ch = idx % CDIM_;
    int bl = idx / CDIM_;
    int l = bl % L_;
    float acc = conv_b[ch];
#pragma unroll
    for (int k = 0; k < DCV; k++) {
        int ls = l + k - (DCV - 1);
        if (ls >= 0)
            acc += g_zx[(size_t)(bl - l + ls) * DIP_ + DI_ + ch] * conv_w[ch * DCV + k];
    }
    g_xBC[(size_t)idx] = acc / (1.f + __expf(-acc));
}

// ---------------- K4: per-chunk inclusive cumsum of dA = dt*A ----------------
__global__ void acs_kernel(const float* __restrict__ A_log) {
    int blk = blockIdx.x;                 // (b*NC + c)*NH + h
    int h = blk % NH_;
    int bc = blk / NH_;
    int c = bc % NC_;
    int b = bc / NC_;
    int t = threadIdx.x;
    __shared__ float s[CH_];
    float A = -__expf(A_log[h]);
    s[t] = g_dtv[(size_t)(b * L_ + c * CH_ + t) * NH_ + h] * A;
    __syncthreads();
    for (int off = 1; off < CH_; off <<= 1) {
        float v = (t >= off) ? s[t - off] : 0.f;
        __syncthreads();
        s[t] += v;
        __syncthreads();
    }
    g_Acs[(size_t)blk * CH_ + t] = s[t];
}

// ---------------- K5: CB[t][s] = sum_n C[t,n]*B[s,n] per (b,chunk) ----------------
__global__ __launch_bounds__(256) void cb_kernel() {
    int z = blockIdx.z;                  // b*NC + c
    int b = z / NC_, c = z % NC_;
    int t0 = blockIdx.y * 64, s0 = blockIdx.x * 64;
    __shared__ float Ct[64][68];         // [n][t]
    __shared__ float Bt[64][68];         // [n][s]
    int tid = threadIdx.x;
    int ti = tid >> 4, si = tid & 15;
    float acc[4][4];
#pragma unroll
    for (int i = 0; i < 4; i++)
#pragma unroll
        for (int j = 0; j < 4; j++) acc[i][j] = 0.f;
    const float* xbase = g_xBC + (size_t)(b * L_ + c * CH_) * CDIM_;
    for (int nh = 0; nh < DS_; nh += 64) {
        __syncthreads();
#pragma unroll
        for (int i = 0; i < 4; i++) {
            int slot = tid + i * 256;              // 0..1023
            int row = slot & 63, ng = (slot >> 6) << 2;
            float4 cv = *(const float4*)(xbase + (size_t)(t0 + row) * CDIM_ + DI_ + DS_ + nh + ng);
            Ct[ng + 0][row] = cv.x; Ct[ng + 1][row] = cv.y;
            Ct[ng + 2][row] = cv.z; Ct[ng + 3][row] = cv.w;
            float4 bv = *(const float4*)(xbase + (size_t)(s0 + row) * CDIM_ + DI_ + nh + ng);
            Bt[ng + 0][row] = bv.x; Bt[ng + 1][row] = bv.y;
            Bt[ng + 2][row] = bv.z; Bt[ng + 3][row] = bv.w;
        }
        __syncthreads();
#pragma unroll 8
        for (int n = 0; n < 64; n++) {
            float a[4], bb[4];
            *(float4*)&a[0]  = *(float4*)&Ct[n][ti * 4];
            *(float4*)&bb[0] = *(float4*)&Bt[n][si * 4];
#pragma unroll
            for (int q = 0; q < 4; q++)
#pragma unroll
                for (int r = 0; r < 4; r++) acc[q][r] += a[q] * bb[r];
        }
    }
#pragma unroll
    for (int q = 0; q < 4; q++) {
        float4 o; o.x = acc[q][0]; o.y = acc[q][1]; o.z = acc[q][2]; o.w = acc[q][3];
        *(float4*)&g_CB[((size_t)z * CH_ + t0 + ti * 4 + q) * CH_ + s0 + si * 4] = o;
    }
}

// ---------------- K6: chunk states ----------------
__global__ __launch_bounds__(256) void state_kernel() {
    int bid = blockIdx.x;                 // (b*NC + c)*NH + h
    int h = bid % NH_;
    int bc = bid / NH_;
    int c = bc % NC_;
    int b = bc / NC_;
    __shared__ float wx[32][64];          // (w*dt*x)[t][p]
    __shared__ float Bt[32][128];         // B[t][n]
    __shared__ float wv[32];
    int tid = threadIdx.x;
    int pi = tid >> 4, ni = tid & 15;
    int p0 = pi * 4, n0 = ni * 8;
    float acc[4][8];
#pragma unroll
    for (int i = 0; i < 4; i++)
#pragma unroll
        for (int j = 0; j < 8; j++) acc[i][j] = 0.f;
    const float* xbc = g_xBC + (size_t)(b * L_ + c * CH_) * CDIM_;
    int ab = ((b * NC_ + c) * NH_ + h) * CH_;
    float acsLast = g_Acs[(size_t)ab + CH_ - 1];

    for (int kt = 0; kt < CH_; kt += 32) {
        __syncthreads();
        if (tid < 32) {
            int r = kt + tid;
            wv[tid] = __expf(acsLast - g_Acs[(size_t)ab + r]) *
                      g_dtv[(size_t)(b * L_ + c * CH_ + r) * NH_ + h];
        }
        __syncthreads();
#pragma unroll
        for (int i = 0; i < 2; i++) {
            int slot = tid + i * 256;             // 0..511
            int row = slot >> 4, p4 = (slot & 15) << 2;
            float4 v = *(const float4*)(xbc + (size_t)(kt + row) * CDIM_ + h * HD_ + p4);
            float wgt = wv[row];
            v.x *= wgt; v.y *= wgt; v.z *= wgt; v.w *= wgt;
            *(float4*)&wx[row][p4] = v;
        }
#pragma unroll
        for (int i = 0; i < 4; i++) {
            int slot = tid + i * 256;             // 0..1023
            int row = slot >> 5, n4 = (slot & 31) << 2;
            *(float4*)&Bt[row][n4] = *(const float4*)(xbc + (size_t)(kt + row) * CDIM_ + DI_ + n4);
        }
        __syncthreads();
#pragma unroll 8
        for (int k = 0; k < 32; k++) {
            float a[4], bb[8];
            *(float4*)&a[0]  = *(float4*)&wx[k][p0];
            *(float4*)&bb[0] = *(float4*)&Bt[k][n0];
            *(float4*)&bb[4] = *(float4*)&Bt[k][n0 + 4];
#pragma unroll
            for (int q = 0; q < 4; q++)
#pragma unroll
                for (int r = 0; r < 8; r++) acc[q][r] += a[q] * bb[r];
        }
    }
    size_t base = (size_t)bid * HD_ * DS_;
#pragma unroll
    for (int q = 0; q < 4; q++) {
        float4 o1, o2;
        o1.x = acc[q][0]; o1.y = acc[q][1]; o1.z = acc[q][2]; o1.w = acc[q][3];
        o2.x = acc[q][4]; o2.y = acc[q][5]; o2.z = acc[q][6]; o2.w = acc[q][7];
        *(float4*)&g_st[base + (size_t)(p0 + q) * DS_ + n0]     = o1;
        *(float4*)&g_st[base + (size_t)(p0 + q) * DS_ + n0 + 4] = o2;
    }
}

// ---------------- K7: inter-chunk state recurrence ----------------
__global__ void rec_kernel() {
    int bid = blockIdx.x;      // b*NH + h
    int h = bid % NH_;
    int b = bid / NH_;
    int tid = threadIdx.x;
    float S[32];
#pragma unroll
    for (int k = 0; k < 32; k++) S[k] = 0.f;
    for (int c = 0; c < NC_; c++) {
        int blk = (b * NC_ + c) * NH_ + h;
        size_t base = (size_t)blk * HD_ * DS_;
        float ef = __expf(g_Acs[(size_t)blk * CH_ + CH_ - 1]);
#pragma unroll
        for (int k = 0; k < 32; k++) {
            size_t e = base + (size_t)k * 256 + tid;
            g_is[e] = S[k];
            S[k] = S[k] * ef + g_st[e];
        }
    }
}

// ---------------- K8: fused Y = Yd + Yo + D*x per (b,chunk,head) ----------------
__global__ __launch_bounds__(256, 1) void y_kernel(const float* __restrict__ D_skip) {
    extern __shared__ float sm[];
    float* x_s   = sm;                   // 256*64 : x[s][p]
    float* w_s   = x_s + 256 * 64;       // 64*256 : weight tile [k][t]
    float* st_s  = w_s + 64 * 256;       // 128*64 : S^T [n][p]
    float* acs_s = st_s + 128 * 64;      // 256
    float* dtv_s = acs_s + 256;          // 256
    float* einv_s = dtv_s + 256;         // 64

    int bid = blockIdx.x;                // (b*NC + c)*NH + h
    int h = bid % NH_;
    int bc = bid / NH_;
    int c = bc % NC_;
    int b = bc / NC_;
    int tid = threadIdx.x;
    int tg = tid >> 3, pg = tid & 7;     // micro 8(t) x 8(p)
    int t = tid;

    const float* xbc = g_xBC + (size_t)(b * L_ + c * CH_) * CDIM_;
    const float* cbrow = g_CB + ((size_t)(b * NC_ + c) * CH_ + t) * CH_;
    const float* isb = g_is + (size_t)bid * HD_ * DS_;
    int ab = bid * CH_;

    for (int slot = tid; slot < 4096; slot += 256) {
        int row = slot >> 4, p4 = (slot & 15) << 2;
        *(float4*)&x_s[row * 64 + p4] = *(const float4*)(xbc + (size_t)row * CDIM_ + h * HD_ + p4);
    }
    for (int slot = tid; slot < 2048; slot += 256) {
        int p = slot & 63, ng = (slot >> 6) << 2;
        float4 v = *(const float4*)(isb + (size_t)p * DS_ + ng);
        st_s[(ng + 0) * 64 + p] = v.x;
        st_s[(ng + 1) * 64 + p] = v.y;
        st_s[(ng + 2) * 64 + p] = v.z;
        st_s[(ng + 3) * 64 + p] = v.w;
    }
    acs_s[tid] = g_Acs[(size_t)ab + tid];
    dtv_s[tid] = g_dtv[(size_t)(b * L_ + c * CH_ + tid) * NH_ + h];

    float acc[8][8];
#pragma unroll
    for (int i = 0; i < 8; i++)
#pragma unroll
        for (int j = 0; j < 8; j++) acc[i][j] = 0.f;

    // Phase A: intra-chunk Yd  (K-tiles of 64 over s)
    for (int k0 = 0; k0 < CH_; k0 += 64) {
        __syncthreads();
        if (tid < 64) {
            int sb = k0 + (tid & 0x30);
            einv_s[tid] = __expf(fminf(acs_s[sb] - acs_s[k0 + tid], 80.f));
        }
        __syncthreads();
#pragma unroll
        for (int sub = 0; sub < 4; sub++) {
            int sbase = k0 + sub * 16;
            if (t >= sbase) {
                float et = __expf(acs_s[t] - acs_s[sbase]);
#pragma unroll
                for (int jj = 0; jj < 16; jj += 4) {
                    float4 cb4 = *(const float4*)(cbrow + sbase + jj);
                    int s0q = sbase + jj;
                    float v0 = et * einv_s[sub * 16 + jj + 0] * cb4.x * dtv_s[s0q + 0];
                    float v1 = et * einv_s[sub * 16 + jj + 1] * cb4.y * dtv_s[s0q + 1];
                    float v2 = et * einv_s[sub * 16 + jj + 2] * cb4.z * dtv_s[s0q + 2];
                    float v3 = et * einv_s[sub * 16 + jj + 3] * cb4.w * dtv_s[s0q + 3];
                    w_s[(sub * 16 + jj + 0) * 256 + t] = (s0q + 0 <= t) ? v0 : 0.f;
                    w_s[(sub * 16 + jj + 1) * 256 + t] = (s0q + 1 <= t) ? v1 : 0.f;
                    w_s[(sub * 16 + jj + 2) * 256 + t] = (s0q + 2 <= t) ? v2 : 0.f;
                    w_s[(sub * 16 + jj + 3) * 256 + t] = (s0q + 3 <= t) ? v3 : 0.f;
                }
            } else {
#pragma unroll
                for (int j = 0; j < 16; j++) w_s[(sub * 16 + j) * 256 + t] = 0.f;
            }
        }
        __syncthreads();
        if (tg * 8 + 7 >= k0) {
#pragma unroll 4
            for (int k = 0; k < 64; k++) {
                float a[8], bb[8];
                *(float4*)&a[0]  = *(float4*)&w_s[k * 256 + tg * 8];
                *(float4*)&a[4]  = *(float4*)&w_s[k * 256 + tg * 8 + 4];
                *(float4*)&bb[0] = *(float4*)&x_s[(k0 + k) * 64 + pg * 8];
                *(float4*)&bb[4] = *(float4*)&x_s[(k0 + k) * 64 + pg * 8 + 4];
#pragma unroll
                for (int mm = 0; mm < 8; mm++)
#pragma unroll
                    for (int nn = 0; nn < 8; nn++) acc[mm][nn] += a[mm] * bb[nn];
            }
        }
    }

    // Phase B: inter-chunk Yo = exp(Acs[t]) * C[t] @ S^T
    float et0 = __expf(acs_s[t]);
    for (int n0 = 0; n0 < DS_; n0 += 64) {
        __syncthreads();
#pragma unroll
        for (int j = 0; j < 64; j += 4) {
            float4 c4 = *(const float4*)(xbc + (size_t)t * CDIM_ + DI_ + DS_ + n0 + j);
            w_s[(j + 0) * 256 + t] = c4.x * et0;
            w_s[(j + 1) * 256 + t] = c4.y * et0;
            w_s[(j + 2) * 256 + t] = c4.z * et0;
            w_s[(j + 3) * 256 + t] = c4.w * et0;
        }
        __syncthreads();
#pragma unroll 4
        for (int k = 0; k < 64; k++) {
            float a[8], bb[8];
            *(float4*)&a[0]  = *(float4*)&w_s[k * 256 + tg * 8];
            *(float4*)&a[4]  = *(float4*)&w_s[k * 256 + tg * 8 + 4];
            *(float4*)&bb[0] = *(float4*)&st_s[(n0 + k) * 64 + pg * 8];
            *(float4*)&bb[4] = *(float4*)&st_s[(n0 + k) * 64 + pg * 8 + 4];
#pragma unroll
            for (int mm = 0; mm < 8; mm++)
#pragma unroll
                for (int nn = 0; nn < 8; nn++) acc[mm][nn] += a[mm] * bb[nn];
        }
    }

    // Epilogue: + D * x, write y
    float dsk = D_skip[h];
#pragma unroll
    for (int mm = 0; mm < 8; mm++) {
        int tt = tg * 8 + mm;
        size_t orow = (size_t)(b * L_ + c * CH_ + tt) * DI_ + h * HD_ + pg * 8;
        float4 o1, o2;
        o1.x = acc[mm][0] + dsk * x_s[tt * 64 + pg * 8 + 0];
        o1.y = acc[mm][1] + dsk * x_s[tt * 64 + pg * 8 + 1];
        o1.z = acc[mm][2] + dsk * x_s[tt * 64 + pg * 8 + 2];
        o1.w = acc[mm][3] + dsk * x_s[tt * 64 + pg * 8 + 3];
        o2.x = acc[mm][4] + dsk * x_s[tt * 64 + pg * 8 + 4];
        o2.y = acc[mm][5] + dsk * x_s[tt * 64 + pg * 8 + 5];
        o2.z = acc[mm][6] + dsk * x_s[tt * 64 + pg * 8 + 6];
        o2.w = acc[mm][7] + dsk * x_s[tt * 64 + pg * 8 + 7];
        *(float4*)&g_y[orow]     = o1;
        *(float4*)&g_y[orow + 4] = o2;
    }
}

// ---------------- K9: gate (silu(z)) + RMSNorm ----------------
__global__ void gate_kernel(const float* __restrict__ norm_w, float* __restrict__ out) {
    int row = blockIdx.x;           // b*L + l
    int tid = threadIdx.x;
    __shared__ float yg_s[DI_];
    __shared__ float red[256];
    float ss = 0.f;
    for (int i = tid; i < DI_; i += 256) {
        float yv = g_y[(size_t)row * DI_ + i];
        float z = g_zx[(size_t)row * DIP_ + i];
        float yg = yv * (z / (1.f + __expf(-z)));
        yg_s[i] = yg;
        ss += yg * yg;
    }
    red[tid] = ss;
    __syncthreads();
    for (int off = 128; off > 0; off >>= 1) {
        if (tid < off) red[tid] += red[tid + off];
        __syncthreads();
    }
    float r = rsqrtf(red[0] / (float)DI_ + 1e-5f);
    for (int i = tid; i < DI_; i += 256)
        out[(size_t)row * DI_ + i] = yg_s[i] * r * norm_w[i];
}

// ---------------- launch ----------------
extern "C" void kernel_launch(void* const* d_in, const int* in_sizes, int n_in,
                              void* d_out, int out_size) {
    const float* u       = (const float*)d_in[0];
    const float* w_in    = (const float*)d_in[1];
    const float* conv_w  = (const float*)d_in[2];
    const float* conv_b  = (const float*)d_in[3];
    const float* dt_bias = (const float*)d_in[4];
    const float* A_log   = (const float*)d_in[5];
    const float* D_skip  = (const float*)d_in[6];
    const float* norm_w  = (const float*)d_in[7];
    float* out = (float*)d_out;

    cudaFuncSetAttribute(y_kernel, cudaFuncAttributeMaxDynamicSharedMemorySize, 166144);

    gemm_tf32_kernel<<<dim3(DIP_ / 64, (B_ * L_) / 128), 256>>>(u, w_in);
    dtg_kernel<<<(B_ * L_) / 64, 256>>>(u, w_in, dt_bias);
    conv_kernel<<<(B_ * L_ * CDIM_) / 256, 256>>>(conv_w, conv_b);
    acs_kernel<<<B_ * NC_ * NH_, CH_>>>(A_log);
    cb_kernel<<<dim3(4, 4, B_ * NC_), 256>>>();
    state_kernel<<<B_ * NC_ * NH_, 256>>>();
    rec_kernel<<<B_ * NH_, 256>>>();
    y_kernel<<<B_ * NC_ * NH_, 256, 166144>>>(D_skip);
    gate_kernel<<<B_ * L_, 256>>>(norm_w, out);
}

// round 4
// speedup vs baseline: 2.0727x; 1.1170x over previous
#include <cuda_runtime.h>
#include <cstdint>
#include <cmath>

#define B_    2
#define L_    2048
#define DM_   2048
#define DIP_  8512
#define DI_   4096
#define CDIM_ 4352
#define NH_   64
#define HD_   64
#define DS_   128
#define CH_   256
#define NC_   8
#define DCV   4
#define GN_   8448            // 33*256: GEMM covers cols [0,8448); dt tail via dtg_kernel

// ---------------- scratch (device globals; no allocation) ----------------
__device__ float g_zx  [(size_t)B_*L_*DIP_];
__device__ float g_xBC [(size_t)B_*L_*CDIM_];
__device__ float g_dtv [(size_t)B_*L_*NH_];
__device__ float g_Acs [(size_t)B_*NC_*NH_*CH_];
__device__ float g_CB  [(size_t)B_*NC_*CH_*CH_];
__device__ float g_st  [(size_t)B_*NC_*NH_*HD_*DS_];
__device__ float g_is  [(size_t)B_*NC_*NH_*HD_*DS_];
__device__ float g_y   [(size_t)B_*L_*DI_];
__device__ __align__(16) float g_ut[(size_t)B_*L_*DM_];   // tf32-rounded u
__device__ __align__(16) float g_wt[(size_t)DM_*GN_];     // tf32-rounded w cols [0,8448)

__device__ __forceinline__ float f2tf32f(float x) {
    uint32_t r;
    asm("cvt.rna.tf32.f32 %0, %1;" : "=r"(r) : "f"(x));
    return __uint_as_float(r);
}
__device__ __forceinline__ uint32_t smem_u32(const void* p) {
    uint32_t a;
    asm("{ .reg .u64 t; cvta.to.shared.u64 t, %1; cvt.u32.u64 %0, t; }" : "=r"(a) : "l"(p));
    return a;
}
__device__ __forceinline__ void cpa16(uint32_t dst, const void* src) {
    asm volatile("cp.async.cg.shared.global [%0], [%1], 16;" :: "r"(dst), "l"(src));
}
#define CPA_COMMIT() asm volatile("cp.async.commit_group;" ::: "memory")
#define CPA_WAIT1()  asm volatile("cp.async.wait_group 1;" ::: "memory")

// ---------------- K0a: u -> tf32-rounded fp32 ----------------
__global__ void uconv_kernel(const float* __restrict__ u) {
    size_t i = (size_t)blockIdx.x * 256 + threadIdx.x;
    float4 v = ((const float4*)u)[i];
    v.x = f2tf32f(v.x); v.y = f2tf32f(v.y);
    v.z = f2tf32f(v.z); v.w = f2tf32f(v.w);
    ((float4*)g_ut)[i] = v;
}

// ---------------- K0b: w -> tf32-rounded fp32, cols [0,8448) ----------------
__global__ void wconv_kernel(const float* __restrict__ w) {
    size_t i = (size_t)blockIdx.x * 256 + threadIdx.x;   // over 2048*2112 float4 slots
    int row = (int)(i / (GN_ / 4));
    int c4  = (int)(i % (GN_ / 4)) * 4;
    float4 v = *(const float4*)(w + (size_t)row * DIP_ + c4);
    v.x = f2tf32f(v.x); v.y = f2tf32f(v.y);
    v.z = f2tf32f(v.z); v.w = f2tf32f(v.w);
    *(float4*)(g_wt + (size_t)row * GN_ + c4) = v;
}

// ---------------- K1: tf32 mma.sync GEMM, 128x128 tile, cp.async 3-stage ----------------
// 8 warps (4m x 2n), warp tile 32x64, K-tile 32
#define ASTG 18432            // 128*36*4
#define BSTG 17408            // 32*136*4
#define STG_ (ASTG + BSTG)    // 35840 per stage
__global__ __launch_bounds__(256, 1) void gemm_tf32_kernel() {
    extern __shared__ char sal[];
    const int tid = threadIdx.x;
    const int m0 = blockIdx.y * 128;
    const int n0 = blockIdx.x * 128;
    const int lane = tid & 31, wid = tid >> 5;
    const int wm = wid >> 1, wn = wid & 1;
    const int grp = lane >> 2, tig = lane & 3;
    const uint32_t sbase = smem_u32(sal);
    const int NKT = DM_ / 32;   // 64

    float acc[2][8][4];
#pragma unroll
    for (int mt = 0; mt < 2; mt++)
#pragma unroll
        for (int nt = 0; nt < 8; nt++)
#pragma unroll
            for (int i = 0; i < 4; i++) acc[mt][nt][i] = 0.f;

    auto issue = [&](int buf, int kt) {
        uint32_t ab = sbase + buf * STG_;
        uint32_t bb = ab + ASTG;
#pragma unroll
        for (int i = 0; i < 4; i++) {
            int slot = tid + i * 256;              // A: 1024 chunks of 16B
            int row = slot >> 3, c = slot & 7;
            cpa16(ab + row * 144 + c * 16,
                  g_ut + (size_t)(m0 + row) * DM_ + kt * 32 + c * 4);
        }
#pragma unroll
        for (int i = 0; i < 4; i++) {
            int slot = tid + i * 256;              // B: 1024 chunks of 16B
            int row = slot >> 5, c = slot & 31;
            cpa16(bb + row * 544 + c * 16,
                  g_wt + (size_t)(kt * 32 + row) * GN_ + n0 + c * 4);
        }
    };

    issue(0, 0); CPA_COMMIT();
    issue(1, 1); CPA_COMMIT();

    for (int kt = 0; kt < NKT; kt++) {
        CPA_WAIT1();
        __syncthreads();
        if (kt + 2 < NKT) issue((kt + 2) % 3, kt + 2);
        CPA_COMMIT();

        const float* As = (const float*)(sal + (kt % 3) * STG_);
        const float* Bs = (const float*)(sal + (kt % 3) * STG_ + ASTG);
#pragma unroll
        for (int ks = 0; ks < 4; ks++) {
            uint32_t a[2][4], b[8][2];
#pragma unroll
            for (int mt = 0; mt < 2; mt++) {
                int r0 = wm * 32 + mt * 16 + grp;
                a[mt][0] = __float_as_uint(As[r0 * 36 + ks * 8 + tig]);
                a[mt][1] = __float_as_uint(As[(r0 + 8) * 36 + ks * 8 + tig]);
                a[mt][2] = __float_as_uint(As[r0 * 36 + ks * 8 + tig + 4]);
                a[mt][3] = __float_as_uint(As[(r0 + 8) * 36 + ks * 8 + tig + 4]);
            }
#pragma unroll
            for (int nt = 0; nt < 8; nt++) {
                int cc = wn * 64 + nt * 8 + grp;
                b[nt][0] = __float_as_uint(Bs[(ks * 8 + tig) * 136 + cc]);
                b[nt][1] = __float_as_uint(Bs[(ks * 8 + tig + 4) * 136 + cc]);
            }
#pragma unroll
            for (int mt = 0; mt < 2; mt++)
#pragma unroll
                for (int nt = 0; nt < 8; nt++) {
                    asm volatile(
                        "mma.sync.aligned.m16n8k8.row.col.f32.tf32.tf32.f32 "
                        "{%0,%1,%2,%3}, {%4,%5,%6,%7}, {%8,%9}, {%0,%1,%2,%3};"
                        : "+f"(acc[mt][nt][0]), "+f"(acc[mt][nt][1]),
                          "+f"(acc[mt][nt][2]), "+f"(acc[mt][nt][3])
                        : "r"(a[mt][0]), "r"(a[mt][1]), "r"(a[mt][2]), "r"(a[mt][3]),
                          "r"(b[nt][0]), "r"(b[nt][1]));
                }
        }
        __syncthreads();
    }

#pragma unroll
    for (int mt = 0; mt < 2; mt++)
#pragma unroll
        for (int nt = 0; nt < 8; nt++) {
            int row = m0 + wm * 32 + mt * 16 + grp;
            int col = n0 + wn * 64 + nt * 8 + tig * 2;
            float2 v0, v1;
            v0.x = acc[mt][nt][0]; v0.y = acc[mt][nt][1];
            v1.x = acc[mt][nt][2]; v1.y = acc[mt][nt][3];
            *(float2*)&g_zx[(size_t)row * DIP_ + col]       = v0;
            *(float2*)&g_zx[(size_t)(row + 8) * DIP_ + col] = v1;
        }
}

// ---------------- K1b: exact fp32 dt = softplus(u @ w_in[:, dt cols] + bias) ----------------
__global__ __launch_bounds__(256) void dtg_kernel(const float* __restrict__ u,
                                                  const float* __restrict__ w,
                                                  const float* __restrict__ dt_bias) {
    __shared__ float Ast[16][68];
    __shared__ float Bst[16][68];
    const int m0 = blockIdx.x * 64;
    const int NOFF = DI_ + CDIM_;
    const int tid = threadIdx.x;
    const int mi = tid >> 4, ni = tid & 15;

    float acc[4][4];
#pragma unroll
    for (int i = 0; i < 4; i++)
#pragma unroll
        for (int j = 0; j < 4; j++) acc[i][j] = 0.f;

    for (int kt = 0; kt < DM_; kt += 16) {
        {
            int m = tid >> 2, kg = (tid & 3) << 2;
            float4 v = *(const float4*)(u + (size_t)(m0 + m) * DM_ + kt + kg);
            Ast[kg + 0][m] = v.x; Ast[kg + 1][m] = v.y;
            Ast[kg + 2][m] = v.z; Ast[kg + 3][m] = v.w;
        }
        {
            int k = tid >> 4, n4 = (tid & 15) << 2;
            *(float4*)&Bst[k][n4] = *(const float4*)(w + (size_t)(kt + k) * DIP_ + NOFF + n4);
        }
        __syncthreads();
#pragma unroll
        for (int k = 0; k < 16; k++) {
            float a[4], b[4];
            *(float4*)&a[0] = *(float4*)&Ast[k][mi * 4];
            *(float4*)&b[0] = *(float4*)&Bst[k][ni * 4];
#pragma unroll
            for (int i = 0; i < 4; i++)
#pragma unroll
                for (int j = 0; j < 4; j++) acc[i][j] += a[i] * b[j];
        }
        __syncthreads();
    }
#pragma unroll
    for (int i = 0; i < 4; i++)
#pragma unroll
        for (int j = 0; j < 4; j++) {
            int h = ni * 4 + j;
            float x = acc[i][j] + dt_bias[h];
            float sp = (x > 20.f) ? x : log1pf(expf(x));
            g_dtv[(size_t)(m0 + mi * 4 + i) * NH_ + h] = sp;
        }
}

// ---------------- K2: causal conv(4) + bias + silu ----------------
__global__ void conv_kernel(const float* __restrict__ conv_w, const float* __restrict__ conv_b) {
    int idx = blockIdx.x * 256 + threadIdx.x;
    int ch = idx % CDIM_;
    int bl = idx / CDIM_;
    int l = bl % L_;
    float acc = conv_b[ch];
#pragma unroll
    for (int k = 0; k < DCV; k++) {
        int ls = l + k - (DCV - 1);
        if (ls >= 0)
            acc += g_zx[(size_t)(bl - l + ls) * DIP_ + DI_ + ch] * conv_w[ch * DCV + k];
    }
    g_xBC[(size_t)idx] = acc / (1.f + __expf(-acc));
}

// ---------------- K4: per-chunk inclusive cumsum of dA ----------------
__global__ void acs_kernel(const float* __restrict__ A_log) {
    int blk = blockIdx.x;
    int h = blk % NH_;
    int bc = blk / NH_;
    int c = bc % NC_;
    int b = bc / NC_;
    int t = threadIdx.x;
    __shared__ float s[CH_];
    float A = -__expf(A_log[h]);
    s[t] = g_dtv[(size_t)(b * L_ + c * CH_ + t) * NH_ + h] * A;
    __syncthreads();
    for (int off = 1; off < CH_; off <<= 1) {
        float v = (t >= off) ? s[t - off] : 0.f;
        __syncthreads();
        s[t] += v;
        __syncthreads();
    }
    g_Acs[(size_t)blk * CH_ + t] = s[t];
}

// ---------------- K5: CB[t][s] per (b,chunk) ----------------
__global__ __launch_bounds__(256) void cb_kernel() {
    int z = blockIdx.z;
    int b = z / NC_, c = z % NC_;
    int t0 = blockIdx.y * 64, s0 = blockIdx.x * 64;
    __shared__ float Ct[64][68];
    __shared__ float Bt[64][68];
    int tid = threadIdx.x;
    int ti = tid >> 4, si = tid & 15;
    float acc[4][4];
#pragma unroll
    for (int i = 0; i < 4; i++)
#pragma unroll
        for (int j = 0; j < 4; j++) acc[i][j] = 0.f;
    const float* xbase = g_xBC + (size_t)(b * L_ + c * CH_) * CDIM_;
    for (int nh = 0; nh < DS_; nh += 64) {
        __syncthreads();
#pragma unroll
        for (int i = 0; i < 4; i++) {
            int slot = tid + i * 256;
            int row = slot & 63, ng = (slot >> 6) << 2;
            float4 cv = *(const float4*)(xbase + (size_t)(t0 + row) * CDIM_ + DI_ + DS_ + nh + ng);
            Ct[ng + 0][row] = cv.x; Ct[ng + 1][row] = cv.y;
            Ct[ng + 2][row] = cv.z; Ct[ng + 3][row] = cv.w;
            float4 bv = *(const float4*)(xbase + (size_t)(s0 + row) * CDIM_ + DI_ + nh + ng);
            Bt[ng + 0][row] = bv.x; Bt[ng + 1][row] = bv.y;
            Bt[ng + 2][row] = bv.z; Bt[ng + 3][row] = bv.w;
        }
        __syncthreads();
#pragma unroll 8
        for (int n = 0; n < 64; n++) {
            float a[4], bb[4];
            *(float4*)&a[0]  = *(float4*)&Ct[n][ti * 4];
            *(float4*)&bb[0] = *(float4*)&Bt[n][si * 4];
#pragma unroll
            for (int q = 0; q < 4; q++)
#pragma unroll
                for (int r = 0; r < 4; r++) acc[q][r] += a[q] * bb[r];
        }
    }
#pragma unroll
    for (int q = 0; q < 4; q++) {
        float4 o; o.x = acc[q][0]; o.y = acc[q][1]; o.z = acc[q][2]; o.w = acc[q][3];
        *(float4*)&g_CB[((size_t)z * CH_ + t0 + ti * 4 + q) * CH_ + s0 + si * 4] = o;
    }
}

// ---------------- K6: chunk states ----------------
__global__ __launch_bounds__(256) void state_kernel() {
    int bid = blockIdx.x;
    int h = bid % NH_;
    int bc = bid / NH_;
    int c = bc % NC_;
    int b = bc / NC_;
    __shared__ float wx[32][64];
    __shared__ float Bt[32][128];
    __shared__ float wv[32];
    int tid = threadIdx.x;
    int pi = tid >> 4, ni = tid & 15;
    int p0 = pi * 4, n0 = ni * 8;
    float acc[4][8];
#pragma unroll
    for (int i = 0; i < 4; i++)
#pragma unroll
        for (int j = 0; j < 8; j++) acc[i][j] = 0.f;
    const float* xbc = g_xBC + (size_t)(b * L_ + c * CH_) * CDIM_;
    int ab = ((b * NC_ + c) * NH_ + h) * CH_;
    float acsLast = g_Acs[(size_t)ab + CH_ - 1];

    for (int kt = 0; kt < CH_; kt += 32) {
        __syncthreads();
        if (tid < 32) {
            int r = kt + tid;
            wv[tid] = __expf(acsLast - g_Acs[(size_t)ab + r]) *
                      g_dtv[(size_t)(b * L_ + c * CH_ + r) * NH_ + h];
        }
        __syncthreads();
#pragma unroll
        for (int i = 0; i < 2; i++) {
            int slot = tid + i * 256;
            int row = slot >> 4, p4 = (slot & 15) << 2;
            float4 v = *(const float4*)(xbc + (size_t)(kt + row) * CDIM_ + h * HD_ + p4);
            float wgt = wv[row];
            v.x *= wgt; v.y *= wgt; v.z *= wgt; v.w *= wgt;
            *(float4*)&wx[row][p4] = v;
        }
#pragma unroll
        for (int i = 0; i < 4; i++) {
            int slot = tid + i * 256;
            int row = slot >> 5, n4 = (slot & 31) << 2;
            *(float4*)&Bt[row][n4] = *(const float4*)(xbc + (size_t)(kt + row) * CDIM_ + DI_ + n4);
        }
        __syncthreads();
#pragma unroll 8
        for (int k = 0; k < 32; k++) {
            float a[4], bb[8];
            *(float4*)&a[0]  = *(float4*)&wx[k][p0];
            *(float4*)&bb[0] = *(float4*)&Bt[k][n0];
            *(float4*)&bb[4] = *(float4*)&Bt[k][n0 + 4];
#pragma unroll
            for (int q = 0; q < 4; q++)
#pragma unroll
                for (int r = 0; r < 8; r++) acc[q][r] += a[q] * bb[r];
        }
    }
    size_t base = (size_t)bid * HD_ * DS_;
#pragma unroll
    for (int q = 0; q < 4; q++) {
        float4 o1, o2;
        o1.x = acc[q][0]; o1.y = acc[q][1]; o1.z = acc[q][2]; o1.w = acc[q][3];
        o2.x = acc[q][4]; o2.y = acc[q][5]; o2.z = acc[q][6]; o2.w = acc[q][7];
        *(float4*)&g_st[base + (size_t)(p0 + q) * DS_ + n0]     = o1;
        *(float4*)&g_st[base + (size_t)(p0 + q) * DS_ + n0 + 4] = o2;
    }
}

// ---------------- K7: inter-chunk state recurrence ----------------
__global__ void rec_kernel() {
    int bid = blockIdx.x;
    int h = bid % NH_;
    int b = bid / NH_;
    int tid = threadIdx.x;
    float S[32];
#pragma unroll
    for (int k = 0; k < 32; k++) S[k] = 0.f;
    for (int c = 0; c < NC_; c++) {
        int blk = (b * NC_ + c) * NH_ + h;
        size_t base = (size_t)blk * HD_ * DS_;
        float ef = __expf(g_Acs[(size_t)blk * CH_ + CH_ - 1]);
#pragma unroll
        for (int k = 0; k < 32; k++) {
            size_t e = base + (size_t)k * 256 + tid;
            g_is[e] = S[k];
            S[k] = S[k] * ef + g_st[e];
        }
    }
}

// ---------------- K8: fused Y = Yd + Yo + D*x ----------------
__global__ __launch_bounds__(256, 1) void y_kernel(const float* __restrict__ D_skip) {
    extern __shared__ float sm[];
    float* x_s   = sm;
    float* w_s   = x_s + 256 * 64;
    float* st_s  = w_s + 64 * 256;
    float* acs_s = st_s + 128 * 64;
    float* dtv_s = acs_s + 256;
    float* einv_s = dtv_s + 256;

    int bid = blockIdx.x;
    int h = bid % NH_;
    int bc = bid / NH_;
    int c = bc % NC_;
    int b = bc / NC_;
    int tid = threadIdx.x;
    int tg = tid >> 3, pg = tid & 7;
    int t = tid;

    const float* xbc = g_xBC + (size_t)(b * L_ + c * CH_) * CDIM_;
    const float* cbrow = g_CB + ((size_t)(b * NC_ + c) * CH_ + t) * CH_;
    const float* isb = g_is + (size_t)bid * HD_ * DS_;
    int ab = bid * CH_;

    for (int slot = tid; slot < 4096; slot += 256) {
        int row = slot >> 4, p4 = (slot & 15) << 2;
        *(float4*)&x_s[row * 64 + p4] = *(const float4*)(xbc + (size_t)row * CDIM_ + h * HD_ + p4);
    }
    for (int slot = tid; slot < 2048; slot += 256) {
        int p = slot & 63, ng = (slot >> 6) << 2;
        float4 v = *(const float4*)(isb + (size_t)p * DS_ + ng);
        st_s[(ng + 0) * 64 + p] = v.x;
        st_s[(ng + 1) * 64 + p] = v.y;
        st_s[(ng + 2) * 64 + p] = v.z;
        st_s[(ng + 3) * 64 + p] = v.w;
    }
    acs_s[tid] = g_Acs[(size_t)ab + tid];
    dtv_s[tid] = g_dtv[(size_t)(b * L_ + c * CH_ + tid) * NH_ + h];

    float acc[8][8];
#pragma unroll
    for (int i = 0; i < 8; i++)
#pragma unroll
        for (int j = 0; j < 8; j++) acc[i][j] = 0.f;

    for (int k0 = 0; k0 < CH_; k0 += 64) {
        __syncthreads();
        if (tid < 64) {
            int sb = k0 + (tid & 0x30);
            einv_s[tid] = __expf(fminf(acs_s[sb] - acs_s[k0 + tid], 80.f));
        }
        __syncthreads();
#pragma unroll
        for (int sub = 0; sub < 4; sub++) {
            int sbase = k0 + sub * 16;
            if (t >= sbase) {
                float et = __expf(acs_s[t] - acs_s[sbase]);
#pragma unroll
                for (int jj = 0; jj < 16; jj += 4) {
                    float4 cb4 = *(const float4*)(cbrow + sbase + jj);
                    int s0q = sbase + jj;
                    float v0 = et * einv_s[sub * 16 + jj + 0] * cb4.x * dtv_s[s0q + 0];
                    float v1 = et * einv_s[sub * 16 + jj + 1] * cb4.y * dtv_s[s0q + 1];
                    float v2 = et * einv_s[sub * 16 + jj + 2] * cb4.z * dtv_s[s0q + 2];
                    float v3 = et * einv_s[sub * 16 + jj + 3] * cb4.w * dtv_s[s0q + 3];
                    w_s[(sub * 16 + jj + 0) * 256 + t] = (s0q + 0 <= t) ? v0 : 0.f;
                    w_s[(sub * 16 + jj + 1) * 256 + t] = (s0q + 1 <= t) ? v1 : 0.f;
                    w_s[(sub * 16 + jj + 2) * 256 + t] = (s0q + 2 <= t) ? v2 : 0.f;
                    w_s[(sub * 16 + jj + 3) * 256 + t] = (s0q + 3 <= t) ? v3 : 0.f;
                }
            } else {
#pragma unroll
                for (int j = 0; j < 16; j++) w_s[(sub * 16 + j) * 256 + t] = 0.f;
            }
        }
        __syncthreads();
        if (tg * 8 + 7 >= k0) {
#pragma unroll 4
            for (int k = 0; k < 64; k++) {
                float a[8], bb[8];
                *(float4*)&a[0]  = *(float4*)&w_s[k * 256 + tg * 8];
                *(float4*)&a[4]  = *(float4*)&w_s[k * 256 + tg * 8 + 4];
                *(float4*)&bb[0] = *(float4*)&x_s[(k0 + k) * 64 + pg * 8];
                *(float4*)&bb[4] = *(float4*)&x_s[(k0 + k) * 64 + pg * 8 + 4];
#pragma unroll
                for (int mm = 0; mm < 8; mm++)
#pragma unroll
                    for (int nn = 0; nn < 8; nn++) acc[mm][nn] += a[mm] * bb[nn];
            }
        }
    }

    float et0 = __expf(acs_s[t]);
    for (int n0 = 0; n0 < DS_; n0 += 64) {
        __syncthreads();
#pragma unroll
        for (int j = 0; j < 64; j += 4) {
            float4 c4 = *(const float4*)(xbc + (size_t)t * CDIM_ + DI_ + DS_ + n0 + j);
            w_s[(j + 0) * 256 + t] = c4.x * et0;
            w_s[(j + 1) * 256 + t] = c4.y * et0;
            w_s[(j + 2) * 256 + t] = c4.z * et0;
            w_s[(j + 3) * 256 + t] = c4.w * et0;
        }
        __syncthreads();
#pragma unroll 4
        for (int k = 0; k < 64; k++) {
            float a[8], bb[8];
            *(float4*)&a[0]  = *(float4*)&w_s[k * 256 + tg * 8];
            *(float4*)&a[4]  = *(float4*)&w_s[k * 256 + tg * 8 + 4];
            *(float4*)&bb[0] = *(float4*)&st_s[(n0 + k) * 64 + pg * 8];
            *(float4*)&bb[4] = *(float4*)&st_s[(n0 + k) * 64 + pg * 8 + 4];
#pragma unroll
            for (int mm = 0; mm < 8; mm++)
#pragma unroll
                for (int nn = 0; nn < 8; nn++) acc[mm][nn] += a[mm] * bb[nn];
        }
    }

    float dsk = D_skip[h];
#pragma unroll
    for (int mm = 0; mm < 8; mm++) {
        int tt = tg * 8 + mm;
        size_t orow = (size_t)(b * L_ + c * CH_ + tt) * DI_ + h * HD_ + pg * 8;
        float4 o1, o2;
        o1.x = acc[mm][0] + dsk * x_s[tt * 64 + pg * 8 + 0];
        o1.y = acc[mm][1] + dsk * x_s[tt * 64 + pg * 8 + 1];
        o1.z = acc[mm][2] + dsk * x_s[tt * 64 + pg * 8 + 2];
        o1.w = acc[mm][3] + dsk * x_s[tt * 64 + pg * 8 + 3];
        o2.x = acc[mm][4] + dsk * x_s[tt * 64 + pg * 8 + 4];
        o2.y = acc[mm][5] + dsk * x_s[tt * 64 + pg * 8 + 5];
        o2.z = acc[mm][6] + dsk * x_s[tt * 64 + pg * 8 + 6];
        o2.w = acc[mm][7] + dsk * x_s[tt * 64 + pg * 8 + 7];
        *(float4*)&g_y[orow]     = o1;
        *(float4*)&g_y[orow + 4] = o2;
    }
}

// ---------------- K9: gate + RMSNorm ----------------
__global__ void gate_kernel(const float* __restrict__ norm_w, float* __restrict__ out) {
    int row = blockIdx.x;
    int tid = threadIdx.x;
    __shared__ float yg_s[DI_];
    __shared__ float red[256];
    float ss = 0.f;
    for (int i = tid; i < DI_; i += 256) {
        float yv = g_y[(size_t)row * DI_ + i];
        float z = g_zx[(size_t)row * DIP_ + i];
        float yg = yv * (z / (1.f + __expf(-z)));
        yg_s[i] = yg;
        ss += yg * yg;
    }
    red[tid] = ss;
    __syncthreads();
    for (int off = 128; off > 0; off >>= 1) {
        if (tid < off) red[tid] += red[tid + off];
        __syncthreads();
    }
    float r = rsqrtf(red[0] / (float)DI_ + 1e-5f);
    for (int i = tid; i < DI_; i += 256)
        out[(size_t)row * DI_ + i] = yg_s[i] * r * norm_w[i];
}

// ---------------- launch ----------------
extern "C" void kernel_launch(void* const* d_in, const int* in_sizes, int n_in,
                              void* d_out, int out_size) {
    const float* u       = (const float*)d_in[0];
    const float* w_in    = (const float*)d_in[1];
    const float* conv_w  = (const float*)d_in[2];
    const float* conv_b  = (const float*)d_in[3];
    const float* dt_bias = (const float*)d_in[4];
    const float* A_log   = (const float*)d_in[5];
    const float* D_skip  = (const float*)d_in[6];
    const float* norm_w  = (const float*)d_in[7];
    float* out = (float*)d_out;

    cudaFuncSetAttribute(y_kernel, cudaFuncAttributeMaxDynamicSharedMemorySize, 166144);
    cudaFuncSetAttribute(gemm_tf32_kernel, cudaFuncAttributeMaxDynamicSharedMemorySize, 3 * STG_);

    uconv_kernel<<<(B_ * L_ * DM_) / 4 / 256, 256>>>(u);
    wconv_kernel<<<(DM_ * GN_) / 4 / 256, 256>>>(w_in);
    gemm_tf32_kernel<<<dim3(GN_ / 128, (B_ * L_) / 128), 256, 3 * STG_>>>();
    dtg_kernel<<<(B_ * L_) / 64, 256>>>(u, w_in, dt_bias);
    conv_kernel<<<(B_ * L_ * CDIM_) / 256, 256>>>(conv_w, conv_b);
    acs_kernel<<<B_ * NC_ * NH_, CH_>>>(A_log);
    cb_kernel<<<dim3(4, 4, B_ * NC_), 256>>>();
    state_kernel<<<B_ * NC_ * NH_, 256>>>();
    rec_kernel<<<B_ * NH_, 256>>>();
    y_kernel<<<B_ * NC_ * NH_, 256, 166144>>>(D_skip);
    gate_kernel<<<B_ * L_, 256>>>(norm_w, out);
}

// round 5
// speedup vs baseline: 2.2849x; 1.1024x over previous
#include <cuda_runtime.h>
#include <cstdint>
#include <cmath>

#define B_    2
#define L_    2048
#define DM_   2048
#define DIP_  8512
#define DI_   4096
#define CDIM_ 4352
#define NH_   64
#define HD_   64
#define DS_   128
#define CH_   256
#define NC_   8
#define DCV   4
#define GN_   8448            // 33*256: GEMM covers cols [0,8448); dt tail via dtg_kernel

// ---------------- scratch (device globals; no allocation) ----------------
__device__ float g_zx  [(size_t)B_*L_*DIP_];
__device__ float g_xBC [(size_t)B_*L_*CDIM_];
__device__ float g_dtv [(size_t)B_*L_*NH_];
__device__ float g_Acs [(size_t)B_*NC_*NH_*CH_];
__device__ float g_CB  [(size_t)B_*NC_*CH_*CH_];
__device__ float g_st  [(size_t)B_*NC_*NH_*HD_*DS_];
__device__ float g_is  [(size_t)B_*NC_*NH_*HD_*DS_];
__device__ float g_y   [(size_t)B_*L_*DI_];
__device__ __align__(16) float g_ut[(size_t)B_*L_*DM_];   // tf32-rounded u
__device__ __align__(16) float g_wt[(size_t)DM_*GN_];     // tf32-rounded w cols [0,8448)

__device__ __forceinline__ float f2tf32f(float x) {
    uint32_t r;
    asm("cvt.rna.tf32.f32 %0, %1;" : "=r"(r) : "f"(x));
    return __uint_as_float(r);
}
__device__ __forceinline__ uint32_t smem_u32(const void* p) {
    uint32_t a;
    asm("{ .reg .u64 t; cvta.to.shared.u64 t, %1; cvt.u32.u64 %0, t; }" : "=r"(a) : "l"(p));
    return a;
}
__device__ __forceinline__ void cpa16(uint32_t dst, const void* src) {
    asm volatile("cp.async.cg.shared.global [%0], [%1], 16;" :: "r"(dst), "l"(src));
}
#define CPA_COMMIT() asm volatile("cp.async.commit_group;" ::: "memory")
#define CPA_WAIT1()  asm volatile("cp.async.wait_group 1;" ::: "memory")

// ---------------- K0a: u -> tf32-rounded fp32 ----------------
__global__ void uconv_kernel(const float* __restrict__ u) {
    size_t i = (size_t)blockIdx.x * 256 + threadIdx.x;
    float4 v = ((const float4*)u)[i];
    v.x = f2tf32f(v.x); v.y = f2tf32f(v.y);
    v.z = f2tf32f(v.z); v.w = f2tf32f(v.w);
    ((float4*)g_ut)[i] = v;
}

// ---------------- K0b: w -> tf32-rounded fp32, cols [0,8448) ----------------
__global__ void wconv_kernel(const float* __restrict__ w) {
    size_t i = (size_t)blockIdx.x * 256 + threadIdx.x;
    int row = (int)(i / (GN_ / 4));
    int c4  = (int)(i % (GN_ / 4)) * 4;
    float4 v = *(const float4*)(w + (size_t)row * DIP_ + c4);
    v.x = f2tf32f(v.x); v.y = f2tf32f(v.y);
    v.z = f2tf32f(v.z); v.w = f2tf32f(v.w);
    *(float4*)(g_wt + (size_t)row * GN_ + c4) = v;
}

// ---------------- K1: tf32 mma.sync GEMM, 128x256 block tile, 3-stage cp.async ----------
// 8 warps (2m x 4n), warp tile 64x64, K-tile 32
#define ASTG 18432            // 128*36*4
#define BSTG 33792            // 32*264*4
#define STG_ (ASTG + BSTG)    // 52224 per stage
__global__ __launch_bounds__(256, 1) void gemm_tf32_kernel() {
    extern __shared__ char sal[];
    const int tid = threadIdx.x;
    const int m0 = blockIdx.y * 128;
    const int n0 = blockIdx.x * 256;
    const int lane = tid & 31, wid = tid >> 5;
    const int wm = wid >> 2, wn = wid & 3;
    const int grp = lane >> 2, tig = lane & 3;
    const uint32_t sbase = smem_u32(sal);
    const int NKT = DM_ / 32;   // 64

    float acc[4][8][4];
#pragma unroll
    for (int mt = 0; mt < 4; mt++)
#pragma unroll
        for (int nt = 0; nt < 8; nt++)
#pragma unroll
            for (int i = 0; i < 4; i++) acc[mt][nt][i] = 0.f;

    auto issue = [&](int buf, int kt) {
        uint32_t ab = sbase + buf * STG_;
        uint32_t bb = ab + ASTG;
#pragma unroll
        for (int i = 0; i < 4; i++) {
            int slot = tid + i * 256;              // A: 1024 chunks (128 rows x 8)
            int row = slot >> 3, c = slot & 7;
            cpa16(ab + row * 144 + c * 16,
                  g_ut + (size_t)(m0 + row) * DM_ + kt * 32 + c * 4);
        }
#pragma unroll
        for (int i = 0; i < 8; i++) {
            int slot = tid + i * 256;              // B: 2048 chunks (32 rows x 64)
            int row = slot >> 6, c = slot & 63;
            cpa16(bb + row * 1056 + c * 16,
                  g_wt + (size_t)(kt * 32 + row) * GN_ + n0 + c * 4);
        }
    };

    issue(0, 0); CPA_COMMIT();
    issue(1, 1); CPA_COMMIT();

    for (int kt = 0; kt < NKT; kt++) {
        CPA_WAIT1();
        __syncthreads();
        if (kt + 2 < NKT) issue((kt + 2) % 3, kt + 2);
        CPA_COMMIT();

        const float* As = (const float*)(sal + (kt % 3) * STG_);
        const float* Bs = (const float*)(sal + (kt % 3) * STG_ + ASTG);
#pragma unroll
        for (int ks = 0; ks < 4; ks++) {
            uint32_t a[4][4], b[8][2];
#pragma unroll
            for (int mt = 0; mt < 4; mt++) {
                int r0 = wm * 64 + mt * 16 + grp;
                a[mt][0] = __float_as_uint(As[r0 * 36 + ks * 8 + tig]);
                a[mt][1] = __float_as_uint(As[(r0 + 8) * 36 + ks * 8 + tig]);
                a[mt][2] = __float_as_uint(As[r0 * 36 + ks * 8 + tig + 4]);
                a[mt][3] = __float_as_uint(As[(r0 + 8) * 36 + ks * 8 + tig + 4]);
            }
#pragma unroll
            for (int nt = 0; nt < 8; nt++) {
                int cc = wn * 64 + nt * 8 + grp;
                b[nt][0] = __float_as_uint(Bs[(ks * 8 + tig) * 264 + cc]);
                b[nt][1] = __float_as_uint(Bs[(ks * 8 + tig + 4) * 264 + cc]);
            }
#pragma unroll
            for (int mt = 0; mt < 4; mt++)
#pragma unroll
                for (int nt = 0; nt < 8; nt++) {
                    asm volatile(
                        "mma.sync.aligned.m16n8k8.row.col.f32.tf32.tf32.f32 "
                        "{%0,%1,%2,%3}, {%4,%5,%6,%7}, {%8,%9}, {%0,%1,%2,%3};"
                        : "+f"(acc[mt][nt][0]), "+f"(acc[mt][nt][1]),
                          "+f"(acc[mt][nt][2]), "+f"(acc[mt][nt][3])
                        : "r"(a[mt][0]), "r"(a[mt][1]), "r"(a[mt][2]), "r"(a[mt][3]),
                          "r"(b[nt][0]), "r"(b[nt][1]));
                }
        }
        __syncthreads();
    }

#pragma unroll
    for (int mt = 0; mt < 4; mt++)
#pragma unroll
        for (int nt = 0; nt < 8; nt++) {
            int row = m0 + wm * 64 + mt * 16 + grp;
            int col = n0 + wn * 64 + nt * 8 + tig * 2;
            float2 v0, v1;
            v0.x = acc[mt][nt][0]; v0.y = acc[mt][nt][1];
            v1.x = acc[mt][nt][2]; v1.y = acc[mt][nt][3];
            *(float2*)&g_zx[(size_t)row * DIP_ + col]       = v0;
            *(float2*)&g_zx[(size_t)(row + 8) * DIP_ + col] = v1;
        }
}

// ---------------- K1b: exact fp32 dt = softplus(u @ w_in[:, dt cols] + bias) ----------
// m-tile 16 -> grid 256 blocks (fixes occ=12.5% launch-bound stall seen in ncu)
__global__ __launch_bounds__(256) void dtg_kernel(const float* __restrict__ u,
                                                  const float* __restrict__ w,
                                                  const float* __restrict__ dt_bias) {
    __shared__ float Ast[16][17];   // [k][m]
    __shared__ float Bst[16][68];   // [k][n]
    const int m0 = blockIdx.x * 16;
    const int NOFF = DI_ + CDIM_;
    const int tid = threadIdx.x;
    const int mi = tid >> 4, ni = tid & 15;   // 16 x 16, each 1m x 4n

    float acc[4] = {0.f, 0.f, 0.f, 0.f};

    for (int kt = 0; kt < DM_; kt += 16) {
        if (tid < 64) {
            int m = tid >> 2, kg = (tid & 3) << 2;
            float4 v = *(const float4*)(u + (size_t)(m0 + m) * DM_ + kt + kg);
            Ast[kg + 0][m] = v.x; Ast[kg + 1][m] = v.y;
            Ast[kg + 2][m] = v.z; Ast[kg + 3][m] = v.w;
        }
        {
            int k = tid >> 4, n4 = (tid & 15) << 2;
            *(float4*)&Bst[k][n4] = *(const float4*)(w + (size_t)(kt + k) * DIP_ + NOFF + n4);
        }
        __syncthreads();
#pragma unroll
        for (int k = 0; k < 16; k++) {
            float a = Ast[k][mi];
            float b[4];
            *(float4*)&b[0] = *(float4*)&Bst[k][ni * 4];
#pragma unroll
            for (int j = 0; j < 4; j++) acc[j] += a * b[j];
        }
        __syncthreads();
    }
#pragma unroll
    for (int j = 0; j < 4; j++) {
        int h = ni * 4 + j;
        float x = acc[j] + dt_bias[h];
        float sp = (x > 20.f) ? x : log1pf(expf(x));
        g_dtv[(size_t)(m0 + mi) * NH_ + h] = sp;
    }
}

// ---------------- K2: causal conv(4) + bias + silu ----------------
__global__ void conv_kernel(const float* __restrict__ conv_w, const float* __restrict__ conv_b) {
    int idx = blockIdx.x * 256 + threadIdx.x;
    int ch = idx % CDIM_;
    int bl = idx / CDIM_;
    int l = bl % L_;
    float acc = conv_b[ch];
#pragma unroll
    for (int k = 0; k < DCV; k++) {
        int ls = l + k - (DCV - 1);
        if (ls >= 0)
            acc += g_zx[(size_t)(bl - l + ls) * DIP_ + DI_ + ch] * conv_w[ch * DCV + k];
    }
    g_xBC[(size_t)idx] = acc / (1.f + __expf(-acc));
}

// ---------------- K4: per-chunk inclusive cumsum of dA ----------------
__global__ void acs_kernel(const float* __restrict__ A_log) {
    int blk = blockIdx.x;
    int h = blk % NH_;
    int bc = blk / NH_;
    int c = bc % NC_;
    int b = bc / NC_;
    int t = threadIdx.x;
    __shared__ float s[CH_];
    float A = -__expf(A_log[h]);
    s[t] = g_dtv[(size_t)(b * L_ + c * CH_ + t) * NH_ + h] * A;
    __syncthreads();
    for (int off = 1; off < CH_; off <<= 1) {
        float v = (t >= off) ? s[t - off] : 0.f;
        __syncthreads();
        s[t] += v;
        __syncthreads();
    }
    g_Acs[(size_t)blk * CH_ + t] = s[t];
}

// ---------------- K5: CB[t][s] per (b,chunk) ----------------
__global__ __launch_bounds__(256) void cb_kernel() {
    int z = blockIdx.z;
    int b = z / NC_, c = z % NC_;
    int t0 = blockIdx.y * 64, s0 = blockIdx.x * 64;
    __shared__ float Ct[64][68];
    __shared__ float Bt[64][68];
    int tid = threadIdx.x;
    int ti = tid >> 4, si = tid & 15;
    float acc[4][4];
#pragma unroll
    for (int i = 0; i < 4; i++)
#pragma unroll
        for (int j = 0; j < 4; j++) acc[i][j] = 0.f;
    const float* xbase = g_xBC + (size_t)(b * L_ + c * CH_) * CDIM_;
    for (int nh = 0; nh < DS_; nh += 64) {
        __syncthreads();
#pragma unroll
        for (int i = 0; i < 4; i++) {
            int slot = tid + i * 256;
            int row = slot & 63, ng = (slot >> 6) << 2;
            float4 cv = *(const float4*)(xbase + (size_t)(t0 + row) * CDIM_ + DI_ + DS_ + nh + ng);
            Ct[ng + 0][row] = cv.x; Ct[ng + 1][row] = cv.y;
            Ct[ng + 2][row] = cv.z; Ct[ng + 3][row] = cv.w;
            float4 bv = *(const float4*)(xbase + (size_t)(s0 + row) * CDIM_ + DI_ + nh + ng);
            Bt[ng + 0][row] = bv.x; Bt[ng + 1][row] = bv.y;
            Bt[ng + 2][row] = bv.z; Bt[ng + 3][row] = bv.w;
        }
        __syncthreads();
#pragma unroll 8
        for (int n = 0; n < 64; n++) {
            float a[4], bb[4];
            *(float4*)&a[0]  = *(float4*)&Ct[n][ti * 4];
            *(float4*)&bb[0] = *(float4*)&Bt[n][si * 4];
#pragma unroll
            for (int q = 0; q < 4; q++)
#pragma unroll
                for (int r = 0; r < 4; r++) acc[q][r] += a[q] * bb[r];
        }
    }
#pragma unroll
    for (int q = 0; q < 4; q++) {
        float4 o; o.x = acc[q][0]; o.y = acc[q][1]; o.z = acc[q][2]; o.w = acc[q][3];
        *(float4*)&g_CB[((size_t)z * CH_ + t0 + ti * 4 + q) * CH_ + s0 + si * 4] = o;
    }
}

// ---------------- K6: chunk states ----------------
__global__ __launch_bounds__(256) void state_kernel() {
    int bid = blockIdx.x;
    int h = bid % NH_;
    int bc = bid / NH_;
    int c = bc % NC_;
    int b = bc / NC_;
    __shared__ float wx[32][64];
    __shared__ float Bt[32][128];
    __shared__ float wv[32];
    int tid = threadIdx.x;
    int pi = tid >> 4, ni = tid & 15;
    int p0 = pi * 4, n0 = ni * 8;
    float acc[4][8];
#pragma unroll
    for (int i = 0; i < 4; i++)
#pragma unroll
        for (int j = 0; j < 8; j++) acc[i][j] = 0.f;
    const float* xbc = g_xBC + (size_t)(b * L_ + c * CH_) * CDIM_;
    int ab = ((b * NC_ + c) * NH_ + h) * CH_;
    float acsLast = g_Acs[(size_t)ab + CH_ - 1];

    for (int kt = 0; kt < CH_; kt += 32) {
        __syncthreads();
        if (tid < 32) {
            int r = kt + tid;
            wv[tid] = __expf(acsLast - g_Acs[(size_t)ab + r]) *
                      g_dtv[(size_t)(b * L_ + c * CH_ + r) * NH_ + h];
        }
        __syncthreads();
#pragma unroll
        for (int i = 0; i < 2; i++) {
            int slot = tid + i * 256;
            int row = slot >> 4, p4 = (slot & 15) << 2;
            float4 v = *(const float4*)(xbc + (size_t)(kt + row) * CDIM_ + h * HD_ + p4);
            float wgt = wv[row];
            v.x *= wgt; v.y *= wgt; v.z *= wgt; v.w *= wgt;
            *(float4*)&wx[row][p4] = v;
        }
#pragma unroll
        for (int i = 0; i < 4; i++) {
            int slot = tid + i * 256;
            int row = slot >> 5, n4 = (slot & 31) << 2;
            *(float4*)&Bt[row][n4] = *(const float4*)(xbc + (size_t)(kt + row) * CDIM_ + DI_ + n4);
        }
        __syncthreads();
#pragma unroll 8
        for (int k = 0; k < 32; k++) {
            float a[4], bb[8];
            *(float4*)&a[0]  = *(float4*)&wx[k][p0];
            *(float4*)&bb[0] = *(float4*)&Bt[k][n0];
            *(float4*)&bb[4] = *(float4*)&Bt[k][n0 + 4];
#pragma unroll
            for (int q = 0; q < 4; q++)
#pragma unroll
                for (int r = 0; r < 8; r++) acc[q][r] += a[q] * bb[r];
        }
    }
    size_t base = (size_t)bid * HD_ * DS_;
#pragma unroll
    for (int q = 0; q < 4; q++) {
        float4 o1, o2;
        o1.x = acc[q][0]; o1.y = acc[q][1]; o1.z = acc[q][2]; o1.w = acc[q][3];
        o2.x = acc[q][4]; o2.y = acc[q][5]; o2.z = acc[q][6]; o2.w = acc[q][7];
        *(float4*)&g_st[base + (size_t)(p0 + q) * DS_ + n0]     = o1;
        *(float4*)&g_st[base + (size_t)(p0 + q) * DS_ + n0 + 4] = o2;
    }
}

// ---------------- K7: inter-chunk state recurrence ----------------
__global__ void rec_kernel() {
    int bid = blockIdx.x;
    int h = bid % NH_;
    int b = bid / NH_;
    int tid = threadIdx.x;
    float S[32];
#pragma unroll
    for (int k = 0; k < 32; k++) S[k] = 0.f;
    for (int c = 0; c < NC_; c++) {
        int blk = (b * NC_ + c) * NH_ + h;
        size_t base = (size_t)blk * HD_ * DS_;
        float ef = __expf(g_Acs[(size_t)blk * CH_ + CH_ - 1]);
#pragma unroll
        for (int k = 0; k < 32; k++) {
            size_t e = base + (size_t)k * 256 + tid;
            g_is[e] = S[k];
            S[k] = S[k] * ef + g_st[e];
        }
    }
}

// ---------------- K8: fused Y = Yd + Yo + D*x ----------------
__global__ __launch_bounds__(256, 1) void y_kernel(const float* __restrict__ D_skip) {
    extern __shared__ float sm[];
    float* x_s   = sm;
    float* w_s   = x_s + 256 * 64;
    float* st_s  = w_s + 64 * 256;
    float* acs_s = st_s + 128 * 64;
    float* dtv_s = acs_s + 256;
    float* einv_s = dtv_s + 256;

    int bid = blockIdx.x;
    int h = bid % NH_;
    int bc = bid / NH_;
    int c = bc % NC_;
    int b = bc / NC_;
    int tid = threadIdx.x;
    int tg = tid >> 3, pg = tid & 7;
    int t = tid;

    const float* xbc = g_xBC + (size_t)(b * L_ + c * CH_) * CDIM_;
    const float* cbrow = g_CB + ((size_t)(b * NC_ + c) * CH_ + t) * CH_;
    const float* isb = g_is + (size_t)bid * HD_ * DS_;
    int ab = bid * CH_;

    for (int slot = tid; slot < 4096; slot += 256) {
        int row = slot >> 4, p4 = (slot & 15) << 2;
        *(float4*)&x_s[row * 64 + p4] = *(const float4*)(xbc + (size_t)row * CDIM_ + h * HD_ + p4);
    }
    for (int slot = tid; slot < 2048; slot += 256) {
        int p = slot & 63, ng = (slot >> 6) << 2;
        float4 v = *(const float4*)(isb + (size_t)p * DS_ + ng);
        st_s[(ng + 0) * 64 + p] = v.x;
        st_s[(ng + 1) * 64 + p] = v.y;
        st_s[(ng + 2) * 64 + p] = v.z;
        st_s[(ng + 3) * 64 + p] = v.w;
    }
    acs_s[tid] = g_Acs[(size_t)ab + tid];
    dtv_s[tid] = g_dtv[(size_t)(b * L_ + c * CH_ + tid) * NH_ + h];

    float acc[8][8];
#pragma unroll
    for (int i = 0; i < 8; i++)
#pragma unroll
        for (int j = 0; j < 8; j++) acc[i][j] = 0.f;

    for (int k0 = 0; k0 < CH_; k0 += 64) {
        __syncthreads();
        if (tid < 64) {
            int sb = k0 + (tid & 0x30);
            einv_s[tid] = __expf(fminf(acs_s[sb] - acs_s[k0 + tid], 80.f));
        }
        __syncthreads();
#pragma unroll
        for (int sub = 0; sub < 4; sub++) {
            int sbase = k0 + sub * 16;
            if (t >= sbase) {
                float et = __expf(acs_s[t] - acs_s[sbase]);
#pragma unroll
                for (int jj = 0; jj < 16; jj += 4) {
                    float4 cb4 = *(const float4*)(cbrow + sbase + jj);
                    int s0q = sbase + jj;
                    float v0 = et * einv_s[sub * 16 + jj + 0] * cb4.x * dtv_s[s0q + 0];
                    float v1 = et * einv_s[sub * 16 + jj + 1] * cb4.y * dtv_s[s0q + 1];
                    float v2 = et * einv_s[sub * 16 + jj + 2] * cb4.z * dtv_s[s0q + 2];
                    float v3 = et * einv_s[sub * 16 + jj + 3] * cb4.w * dtv_s[s0q + 3];
                    w_s[(sub * 16 + jj + 0) * 256 + t] = (s0q + 0 <= t) ? v0 : 0.f;
                    w_s[(sub * 16 + jj + 1) * 256 + t] = (s0q + 1 <= t) ? v1 : 0.f;
                    w_s[(sub * 16 + jj + 2) * 256 + t] = (s0q + 2 <= t) ? v2 : 0.f;
                    w_s[(sub * 16 + jj + 3) * 256 + t] = (s0q + 3 <= t) ? v3 : 0.f;
                }
            } else {
#pragma unroll
                for (int j = 0; j < 16; j++) w_s[(sub * 16 + j) * 256 + t] = 0.f;
            }
        }
        __syncthreads();
        if (tg * 8 + 7 >= k0) {
#pragma unroll 4
            for (int k = 0; k < 64; k++) {
                float a[8], bb[8];
                *(float4*)&a[0]  = *(float4*)&w_s[k * 256 + tg * 8];
                *(float4*)&a[4]  = *(float4*)&w_s[k * 256 + tg * 8 + 4];
                *(float4*)&bb[0] = *(float4*)&x_s[(k0 + k) * 64 + pg * 8];
                *(float4*)&bb[4] = *(float4*)&x_s[(k0 + k) * 64 + pg * 8 + 4];
#pragma unroll
                for (int mm = 0; mm < 8; mm++)
#pragma unroll
                    for (int nn = 0; nn < 8; nn++) acc[mm][nn] += a[mm] * bb[nn];
            }
        }
    }

    float et0 = __expf(acs_s[t]);
    for (int n0 = 0; n0 < DS_; n0 += 64) {
        __syncthreads();
#pragma unroll
        for (int j = 0; j < 64; j += 4) {
            float4 c4 = *(const float4*)(xbc + (size_t)t * CDIM_ + DI_ + DS_ + n0 + j);
            w_s[(j + 0) * 256 + t] = c4.x * et0;
            w_s[(j + 1) * 256 + t] = c4.y * et0;
            w_s[(j + 2) * 256 + t] = c4.z * et0;
            w_s[(j + 3) * 256 + t] = c4.w * et0;
        }
        __syncthreads();
#pragma unroll 4
        for (int k = 0; k < 64; k++) {
            float a[8], bb[8];
            *(float4*)&a[0]  = *(float4*)&w_s[k * 256 + tg * 8];
            *(float4*)&a[4]  = *(float4*)&w_s[k * 256 + tg * 8 + 4];
            *(float4*)&bb[0] = *(float4*)&st_s[(n0 + k) * 64 + pg * 8];
            *(float4*)&bb[4] = *(float4*)&st_s[(n0 + k) * 64 + pg * 8 + 4];
#pragma unroll
            for (int mm = 0; mm < 8; mm++)
#pragma unroll
                for (int nn = 0; nn < 8; nn++) acc[mm][nn] += a[mm] * bb[nn];
        }
    }

    float dsk = D_skip[h];
#pragma unroll
    for (int mm = 0; mm < 8; mm++) {
        int tt = tg * 8 + mm;
        size_t orow = (size_t)(b * L_ + c * CH_ + tt) * DI_ + h * HD_ + pg * 8;
        float4 o1, o2;
        o1.x = acc[mm][0] + dsk * x_s[tt * 64 + pg * 8 + 0];
        o1.y = acc[mm][1] + dsk * x_s[tt * 64 + pg * 8 + 1];
        o1.z = acc[mm][2] + dsk * x_s[tt * 64 + pg * 8 + 2];
        o1.w = acc[mm][3] + dsk * x_s[tt * 64 + pg * 8 + 3];
        o2.x = acc[mm][4] + dsk * x_s[tt * 64 + pg * 8 + 4];
        o2.y = acc[mm][5] + dsk * x_s[tt * 64 + pg * 8 + 5];
        o2.z = acc[mm][6] + dsk * x_s[tt * 64 + pg * 8 + 6];
        o2.w = acc[mm][7] + dsk * x_s[tt * 64 + pg * 8 + 7];
        *(float4*)&g_y[orow]     = o1;
        *(float4*)&g_y[orow + 4] = o2;
    }
}

// ---------------- K9: gate + RMSNorm ----------------
__global__ void gate_kernel(const float* __restrict__ norm_w, float* __restrict__ out) {
    int row = blockIdx.x;
    int tid = threadIdx.x;
    __shared__ float yg_s[DI_];
    __shared__ float red[256];
    float ss = 0.f;
    for (int i = tid; i < DI_; i += 256) {
        float yv = g_y[(size_t)row * DI_ + i];
        float z = g_zx[(size_t)row * DIP_ + i];
        float yg = yv * (z / (1.f + __expf(-z)));
        yg_s[i] = yg;
        ss += yg * yg;
    }
    red[tid] = ss;
    __syncthreads();
    for (int off = 128; off > 0; off >>= 1) {
        if (tid < off) red[tid] += red[tid + off];
        __syncthreads();
    }
    float r = rsqrtf(red[0] / (float)DI_ + 1e-5f);
    for (int i = tid; i < DI_; i += 256)
        out[(size_t)row * DI_ + i] = yg_s[i] * r * norm_w[i];
}

// ---------------- launch ----------------
extern "C" void kernel_launch(void* const* d_in, const int* in_sizes, int n_in,
                              void* d_out, int out_size) {
    const float* u       = (const float*)d_in[0];
    const float* w_in    = (const float*)d_in[1];
    const float* conv_w  = (const float*)d_in[2];
    const float* conv_b  = (const float*)d_in[3];
    const float* dt_bias = (const float*)d_in[4];
    const float* A_log   = (const float*)d_in[5];
    const float* D_skip  = (const float*)d_in[6];
    const float* norm_w  = (const float*)d_in[7];
    float* out = (float*)d_out;

    cudaFuncSetAttribute(y_kernel, cudaFuncAttributeMaxDynamicSharedMemorySize, 166144);
    cudaFuncSetAttribute(gemm_tf32_kernel, cudaFuncAttributeMaxDynamicSharedMemorySize, 3 * STG_);

    uconv_kernel<<<(B_ * L_ * DM_) / 4 / 256, 256>>>(u);
    wconv_kernel<<<(DM_ * GN_) / 4 / 256, 256>>>(w_in);
    gemm_tf32_kernel<<<dim3(GN_ / 256, (B_ * L_) / 128), 256, 3 * STG_>>>();
    dtg_kernel<<<(B_ * L_) / 16, 256>>>(u, w_in, dt_bias);
    conv_kernel<<<(B_ * L_ * CDIM_) / 256, 256>>>(conv_w, conv_b);
    acs_kernel<<<B_ * NC_ * NH_, CH_>>>(A_log);
    cb_kernel<<<dim3(4, 4, B_ * NC_), 256>>>();
    state_kernel<<<B_ * NC_ * NH_, 256>>>();
    rec_kernel<<<B_ * NH_, 256>>>();
    y_kernel<<<B_ * NC_ * NH_, 256, 166144>>>(D_skip);
    gate_kernel<<<B_ * L_, 256>>>(norm_w, out);
}